// round 12
// baseline (speedup 1.0000x reference)
#include <cuda_runtime.h>
#include <math.h>
#include <cstdint>

#define T_LEN   16384
#define NATOMS  512
#define ALEN    512
#define BATCH   8
#define NBLK    16
#define BLKSZ   1024
#define SIGL    1536
#define N_ITER  32
#define EPS_N   1e-8f

// full-conv tiling (256 threads, 8 warps = 2m x 4n) — round-10 proven config
#define TM 128
#define KC 64
#define NCHUNK (ALEN / KC)
#define APAD 68
#define TNP 128
#define NI  (TNP / 32)
#define SWIN (TNP + ALEN)
#define SSTR (SWIN + 8)
#define CONV_SMEM ((4 * TM * APAD + 2 * SSTR) * 4)       // 144448
// loop kernel
#define KSTR 516
#define SSL  1544
#define LOOP_SMEM ((2 * 32 * KSTR + 2 * SSL) * 4 + 4096) // 148544
#define PCTAS 128
#define GRPSZ 16

// ---------------- device-global scratch ----------------
__device__ float g_dn[NATOMS * ALEN];
__device__ __align__(16) uint32_t g_dtf[2 * NATOMS * ALEN];
__device__ float g_fm[(size_t)BATCH * NATOMS * T_LEN];            // 256 MB
__device__ unsigned long long g_bmaxp[BATCH * NATOMS * NBLK];     // packed (val,flat) keys
__device__ unsigned long long g_best[N_ITER][BATCH];
__device__ unsigned g_cnt8[BATCH] = {0};
__device__ unsigned g_gen8[BATCH] = {0};

// ---------------- helpers ----------------
__device__ __forceinline__ uint32_t f2tf32(float v) {
    uint32_t r;
    asm("cvt.rna.tf32.f32 %0, %1;" : "=r"(r) : "f"(v));
    return r;
}
__device__ __forceinline__ void mma8(float* c, const uint32_t* a, const uint32_t* b) {
    asm volatile(
        "mma.sync.aligned.m16n8k8.row.col.f32.tf32.tf32.f32 "
        "{%0,%1,%2,%3}, {%4,%5,%6,%7}, {%8,%9}, {%0,%1,%2,%3};"
        : "+f"(c[0]), "+f"(c[1]), "+f"(c[2]), "+f"(c[3])
        : "r"(a[0]), "r"(a[1]), "r"(a[2]), "r"(a[3]), "r"(b[0]), "r"(b[1]));
}
#define CP_COMMIT() asm volatile("cp.async.commit_group;" ::: "memory")
#define CP_WAIT0()  asm volatile("cp.async.wait_group 0;" ::: "memory")
#define CP_WAIT1()  asm volatile("cp.async.wait_group 1;" ::: "memory")

// monotonic float->uint key; low word = 0xFFFFFFFF - flat (first-on-tie via max)
__device__ __forceinline__ unsigned long long pack_key(float v, unsigned flat) {
    unsigned u = __float_as_uint(v);
    unsigned key = (u & 0x80000000u) ? ~u : (u | 0x80000000u);
    return ((unsigned long long)key << 32) | (0xFFFFFFFFu - flat);
}

__device__ __forceinline__ void stage_chunk_async(uint32_t* sAbuf, int n0, int a0, int tid) {
    #pragma unroll
    for (int e = tid; e < TM * 16; e += 256) {
        int kq = e & 15, n = e >> 4;
        size_t gi = (size_t)(n0 + n) * ALEN + a0 + kq * 4;
        uint32_t d0 = (uint32_t)__cvta_generic_to_shared(&sAbuf[n * APAD + kq * 4]);
        uint32_t d1 = (uint32_t)__cvta_generic_to_shared(&sAbuf[TM * APAD + n * APAD + kq * 4]);
        asm volatile("cp.async.cg.shared.global [%0], [%1], 16;" :: "r"(d0), "l"(&g_dtf[gi]) : "memory");
        asm volatile("cp.async.cg.shared.global [%0], [%1], 16;" :: "r"(d1), "l"(&g_dtf[NATOMS * ALEN + gi]) : "memory");
    }
}

// group-local barrier
__device__ __forceinline__ void gsync_grp(int grp) {
    __syncthreads();
    if (threadIdx.x == 0) {
        unsigned gen = atomicAdd(&g_gen8[grp], 0u);
        __threadfence();
        if (atomicInc(&g_cnt8[grp], GRPSZ - 1) == GRPSZ - 1) {
            atomicAdd(&g_gen8[grp], 1u);
        } else {
            while (atomicAdd(&g_gen8[grp], 0u) == gen) __nanosleep(32);
        }
        __threadfence();
    }
    __syncthreads();
}

// ---------------- setup: normalize + tf32 splits ----------------
__global__ void k_norm(const float* __restrict__ d) {
    int n = blockIdx.x;
    int tid = threadIdx.x;
    __shared__ float red[256];
    float s = 0.f;
    for (int a = tid; a < ALEN; a += 256) { float v = d[n * ALEN + a]; s += v * v; }
    red[tid] = s; __syncthreads();
    for (int st = 128; st > 0; st >>= 1) {
        if (tid < st) red[tid] += red[tid + st];
        __syncthreads();
    }
    float inv = 1.0f / (sqrtf(red[0]) + EPS_N);
    for (int a = tid; a < ALEN; a += 256) {
        float v = d[n * ALEN + a] * inv;
        g_dn[n * ALEN + a] = v;
        uint32_t big = f2tf32(v);
        g_dtf[n * ALEN + a] = big;
        g_dtf[NATOMS * ALEN + n * ALEN + a] = f2tf32(v - __uint_as_float(big));
    }
}

__global__ void k_init_out(const float* __restrict__ x, float* __restrict__ out) {
    int i = blockIdx.x * blockDim.x + threadIdx.x;
    int n = BATCH * T_LEN;
    if (i < n) { out[i] = x[i]; out[n + i] = 0.f; }
    if (i < N_ITER * BATCH) ((unsigned long long*)g_best)[i] = 0ull;
}

// ---------------- full correlation (3xTF32, cp.async double-buffered, 256 thr) ----------------
__global__ __launch_bounds__(256, 1) void k_conv_full(const float* __restrict__ x) {
    extern __shared__ __align__(16) uint32_t sm[];
    uint32_t* sA = sm;
    uint32_t* sS = sm + 4 * TM * APAD;

    const int b  = blockIdx.z;
    const int n0 = blockIdx.y * TM;
    const int t0 = blockIdx.x * TNP;
    const int tid = threadIdx.x;
    const int lane = tid & 31;
    const int wm = (tid >> 5) & 1;
    const int wn = tid >> 6;
    const int g = lane >> 2;
    const int tig = lane & 3;

    const float* sig = x + (size_t)b * T_LEN;

    stage_chunk_async(sA, n0, 0, tid);
    CP_COMMIT();

    for (int i = tid; i < SWIN; i += 256) {
        int gi = t0 + i;
        float v = (gi < T_LEN) ? sig[gi] : 0.f;
        uint32_t big = f2tf32(v);
        sS[i] = big;
        sS[SSTR + i] = f2tf32(v - __uint_as_float(big));
    }

    float acc[4][NI][4];
    #pragma unroll
    for (int mi = 0; mi < 4; mi++)
        #pragma unroll
        for (int ni = 0; ni < NI; ni++)
            #pragma unroll
            for (int q = 0; q < 4; q++) acc[mi][ni][q] = 0.f;

    for (int i = 0; i < NCHUNK; i++) {
        if (i + 1 < NCHUNK) {
            stage_chunk_async(sA + ((i + 1) & 1) * 2 * TM * APAD, n0, (i + 1) * KC, tid);
            CP_COMMIT();
            CP_WAIT1();
        } else {
            CP_WAIT0();
        }
        __syncthreads();
        const uint32_t* base = sA + (i & 1) * 2 * TM * APAD;
        const int a0 = i * KC;

        #pragma unroll
        for (int kk = 0; kk < KC / 8; kk++) {
            const int col = kk * 8 + tig;
            uint32_t Ab[4][4], As[4][4], Bb[NI][2], Bs[NI][2];
            #pragma unroll
            for (int mi = 0; mi < 4; mi++) {
                int rm = wm * 64 + mi * 16 + g;
                const uint32_t* p = &base[rm * APAD + col];
                Ab[mi][0] = p[0];
                Ab[mi][1] = p[8 * APAD];
                Ab[mi][2] = p[4];
                Ab[mi][3] = p[8 * APAD + 4];
                const uint32_t* q = p + TM * APAD;
                As[mi][0] = q[0];
                As[mi][1] = q[8 * APAD];
                As[mi][2] = q[4];
                As[mi][3] = q[8 * APAD + 4];
            }
            #pragma unroll
            for (int ni = 0; ni < NI; ni++) {
                int idx = wn * (TNP / 4) + ni * 8 + g + a0 + col;
                Bb[ni][0] = sS[idx];
                Bb[ni][1] = sS[idx + 4];
                Bs[ni][0] = sS[SSTR + idx];
                Bs[ni][1] = sS[SSTR + idx + 4];
            }
            #pragma unroll
            for (int mi = 0; mi < 4; mi++)
                #pragma unroll
                for (int ni = 0; ni < NI; ni++) {
                    mma8(acc[mi][ni], As[mi], Bb[ni]);
                    mma8(acc[mi][ni], Ab[mi], Bs[ni]);
                    mma8(acc[mi][ni], Ab[mi], Bb[ni]);
                }
        }
        __syncthreads();
    }

    #pragma unroll
    for (int mi = 0; mi < 4; mi++) {
        int n1 = n0 + wm * 64 + mi * 16 + g;
        float* row1 = g_fm + ((size_t)(b * NATOMS + n1)) * T_LEN;
        float* row2 = row1 + 8 * (size_t)T_LEN;
        #pragma unroll
        for (int ni = 0; ni < NI; ni++) {
            int tc = t0 + wn * (TNP / 4) + ni * 8 + tig * 2;
            *(float2*)(row1 + tc) = make_float2(acc[mi][ni][0], acc[mi][ni][1]);
            *(float2*)(row2 + tc) = make_float2(acc[mi][ni][2], acc[mi][ni][3]);
        }
    }
}

// ---------------- initial block-max: packed keys, no atomics ----------------
__global__ __launch_bounds__(256) void k_bmax_init() {
    int b = blockIdx.z, n = blockIdx.y, bl = blockIdx.x;
    const float* row = &g_fm[((size_t)(b * NATOMS + n)) * T_LEN + bl * BLKSZ];
    int tid = threadIdx.x;
    float4 v = *reinterpret_cast<const float4*>(&row[tid * 4]);
    float bv = v.x; int bt = tid * 4;
    if (v.y > bv) { bv = v.y; bt = tid * 4 + 1; }
    if (v.z > bv) { bv = v.z; bt = tid * 4 + 2; }
    if (v.w > bv) { bv = v.w; bt = tid * 4 + 3; }
    __shared__ float sv[256];
    __shared__ int   st[256];
    sv[tid] = bv; st[tid] = bt;
    __syncthreads();
    for (int s = 128; s > 0; s >>= 1) {
        if (tid < s) {
            if (sv[tid + s] > sv[tid] || (sv[tid + s] == sv[tid] && st[tid + s] < st[tid])) {
                sv[tid] = sv[tid + s]; st[tid] = st[tid + s];
            }
        }
        __syncthreads();
    }
    if (tid == 0) {
        int tabs = bl * BLKSZ + st[0];
        g_bmaxp[(b * NATOMS + n) * NBLK + bl] =
            pack_key(sv[0], (unsigned)(n * T_LEN + tabs));
    }
}

// ---------------- persistent loop: 1 barrier/iter, smem bmax, predicated MMA ----------------
__global__ __launch_bounds__(256, 1) void k_loop(float* __restrict__ out) {
    extern __shared__ __align__(16) uint32_t sm[];
    uint32_t* sA = sm;                                    // [2 splits][32 n][KSTR]
    uint32_t* sS = sm + 2 * 32 * KSTR;                    // [2 splits][SSL]
    unsigned long long* sBK = (unsigned long long*)(sm + 2 * 32 * KSTR + 2 * SSL);  // [512]
    __shared__ unsigned long long s_part[8];
    __shared__ unsigned long long s_best;

    const int grp = blockIdx.x >> 4;
    const int mem = blockIdx.x & 15;
    const int n0 = mem * 32;
    const int tid = threadIdx.x;
    const int wid = tid >> 5;
    const int lane = tid & 31;
    const int g = lane >> 2;
    const int tig = lane & 3;

    // stage dictionary slice once
    for (int e = tid; e < 2 * 32 * 128; e += 256) {
        int sp = e >> 12;
        int r  = (e >> 7) & 31;
        int kq = e & 127;
        size_t gi = (size_t)sp * NATOMS * ALEN + (size_t)(n0 + r) * ALEN + kq * 4;
        uint32_t dst = (uint32_t)__cvta_generic_to_shared(&sA[sp * 32 * KSTR + r * KSTR + kq * 4]);
        asm volatile("cp.async.cg.shared.global [%0], [%1], 16;" :: "r"(dst), "l"(&g_dtf[gi]) : "memory");
    }
    CP_COMMIT();

    // load own packed block-max keys into smem
    for (int e = tid; e < NATOMS; e += 256)
        sBK[e] = g_bmaxp[(grp * NATOMS + n0) * NBLK + e];
    CP_WAIT0();
    __syncthreads();

    // initial scan -> g_best[0]
    {
        unsigned long long best = sBK[tid];
        unsigned long long o2 = sBK[tid + 256];
        if (o2 > best) best = o2;
        #pragma unroll
        for (int o = 16; o > 0; o >>= 1) {
            unsigned long long ok = __shfl_down_sync(0xFFFFFFFFu, best, o);
            if (ok > best) best = ok;
        }
        if (lane == 0) s_part[wid] = best;
        __syncthreads();
        if (wid == 0) {
            unsigned long long b2 = (lane < 8) ? s_part[lane] : 0ull;
            #pragma unroll
            for (int o = 4; o > 0; o >>= 1) {
                unsigned long long ok = __shfl_down_sync(0xFFFFFFFFu, b2, o);
                if (ok > b2) b2 = ok;
            }
            if (lane == 0) atomicMax(&g_best[0][grp], b2);
        }
    }
    gsync_grp(grp);

    for (int it = 0; it < N_ITER; it++) {
        // decode winner
        if (tid == 0) s_best = *((volatile unsigned long long*)&g_best[it][grp]);
        __syncthreads();
        unsigned long long w = s_best;
        unsigned key = (unsigned)(w >> 32);
        unsigned uv = (key & 0x80000000u) ? (key & 0x7FFFFFFFu) : ~key;
        float v = __uint_as_float(uv);
        unsigned flat = 0xFFFFFFFFu - (unsigned)(w & 0xFFFFFFFFu);
        int n = (int)(flat >> 14);
        int t = (int)(flat & (T_LEN - 1));
        int L = min(t + ALEN, T_LEN - 1) - t;   // ref clips: position T-1 never written

        if (mem == 0) {
            float* res = out + (size_t)grp * T_LEN;
            float* rec = out + (size_t)(BATCH + grp) * T_LEN;
            for (int u = tid; u < L; u += 256) {
                float wv = v * g_dn[n * ALEN + u];
                res[t + u] -= wv;
                rec[t + u] += wv;
            }
        }
        if (it == N_ITER - 1) return;

        if (L > 0) {
            int toff = t - (ALEN - 1);
            // tf32 splits of delta signal, built directly from g_dn
            for (int i = tid; i < SIGL; i += 256) {
                int j = i - (ALEN - 1);
                float sv = (j >= 0 && j < L) ? v * g_dn[n * ALEN + j] : 0.f;
                uint32_t big = f2tf32(sv);
                sS[i] = big;
                sS[SSL + i] = f2tf32(sv - __uint_as_float(big));
            }
            __syncthreads();

            #pragma unroll
            for (int pass = 0; pass < 2; pass++) {
                int tw = pass * 512 + wid * 64;
                int klo = max(0, (ALEN - 1) - (tw + 63)) & ~7;
                int khi = min(ALEN, (ALEN - 1) + L - tw);
                khi = (khi + 7) & ~7;
                if (klo >= khi) continue;

                float acc[2][8][4];
                #pragma unroll
                for (int mi = 0; mi < 2; mi++)
                    #pragma unroll
                    for (int ni = 0; ni < 8; ni++)
                        #pragma unroll
                        for (int q = 0; q < 4; q++) acc[mi][ni][q] = 0.f;

                for (int k0 = klo; k0 < khi; k0 += 8) {
                    int col = k0 + tig;
                    uint32_t Ab[2][4], As[2][4];
                    #pragma unroll
                    for (int mi = 0; mi < 2; mi++) {
                        const uint32_t* p = &sA[(mi * 16 + g) * KSTR + col];
                        Ab[mi][0] = p[0];
                        Ab[mi][1] = p[8 * KSTR];
                        Ab[mi][2] = p[4];
                        Ab[mi][3] = p[8 * KSTR + 4];
                        const uint32_t* q = p + 32 * KSTR;
                        As[mi][0] = q[0];
                        As[mi][1] = q[8 * KSTR];
                        As[mi][2] = q[4];
                        As[mi][3] = q[8 * KSTR + 4];
                    }
                    #pragma unroll
                    for (int ni = 0; ni < 8; ni++) {
                        int tlo = tw + ni * 8;
                        // frag touches sS indices [tlo+k0, tlo+k0+14]; support [511, 511+L)
                        if (tlo + k0 + 14 >= (ALEN - 1) && tlo + k0 <= (ALEN - 2) + L) {
                            uint32_t Bb[2], Bs[2];
                            int idx = tlo + g + col;
                            Bb[0] = sS[idx];
                            Bb[1] = sS[idx + 4];
                            Bs[0] = sS[SSL + idx];
                            Bs[1] = sS[SSL + idx + 4];
                            #pragma unroll
                            for (int mi = 0; mi < 2; mi++) {
                                mma8(acc[mi][ni], As[mi], Bb);
                                mma8(acc[mi][ni], Ab[mi], Bs);
                                mma8(acc[mi][ni], Ab[mi], Bb);
                            }
                        }
                    }
                }

                #pragma unroll
                for (int mi = 0; mi < 2; mi++) {
                    int n1 = n0 + mi * 16 + g;
                    float* row1 = g_fm + ((size_t)(grp * NATOMS + n1)) * T_LEN;
                    float* row2 = row1 + 8 * (size_t)T_LEN;
                    #pragma unroll
                    for (int ni = 0; ni < 8; ni++) {
                        int tt = toff + tw + ni * 8 + tig * 2;
                        if (tt >= 0 && tt < T_LEN)         row1[tt]     -= acc[mi][ni][0];
                        if (tt + 1 >= 0 && tt + 1 < T_LEN) row1[tt + 1] -= acc[mi][ni][1];
                        if (tt >= 0 && tt < T_LEN)         row2[tt]     -= acc[mi][ni][2];
                        if (tt + 1 >= 0 && tt + 1 < T_LEN) row2[tt + 1] -= acc[mi][ni][3];
                    }
                }
            }
            __syncthreads();   // delta stores visible CTA-wide

            // refresh touched block maxima -> smem keys
            {
                int lo = max(0, t - (ALEN - 1));
                int hi = min(T_LEN - 1, t + (ALEN - 1));
                int bl0 = lo >> 10, bl1 = hi >> 10;
                for (int u = wid; u < 64; u += 8) {
                    int r = u >> 1;
                    int which = u & 1;
                    if (which && bl1 == bl0) continue;
                    int bl = which ? bl1 : bl0;
                    const float* row = &g_fm[((size_t)(grp * NATOMS + n0 + r)) * T_LEN + bl * BLKSZ];
                    float bv = -3.402823466e38f;
                    int bt = 0x7FFFFFFF;
                    #pragma unroll
                    for (int i = 0; i < 8; i++) {
                        int base = (i * 32 + lane) * 4;
                        float4 vv = *(const float4*)&row[base];
                        if (vv.x > bv) { bv = vv.x; bt = base; }
                        if (vv.y > bv) { bv = vv.y; bt = base + 1; }
                        if (vv.z > bv) { bv = vv.z; bt = base + 2; }
                        if (vv.w > bv) { bv = vv.w; bt = base + 3; }
                    }
                    #pragma unroll
                    for (int o = 16; o > 0; o >>= 1) {
                        float ov = __shfl_down_sync(0xFFFFFFFFu, bv, o);
                        int   ot = __shfl_down_sync(0xFFFFFFFFu, bt, o);
                        if (ov > bv || (ov == bv && ot < bt)) { bv = ov; bt = ot; }
                    }
                    if (lane == 0)
                        sBK[r * NBLK + bl] =
                            pack_key(bv, (unsigned)((n0 + r) * T_LEN + bl * BLKSZ + bt));
                }
            }
        }
        __syncthreads();   // sBK updates visible

        // scan own keys -> contribute winner for it+1
        {
            unsigned long long best = sBK[tid];
            unsigned long long o2 = sBK[tid + 256];
            if (o2 > best) best = o2;
            #pragma unroll
            for (int o = 16; o > 0; o >>= 1) {
                unsigned long long ok = __shfl_down_sync(0xFFFFFFFFu, best, o);
                if (ok > best) best = ok;
            }
            if (lane == 0) s_part[wid] = best;
            __syncthreads();
            if (wid == 0) {
                unsigned long long b2 = (lane < 8) ? s_part[lane] : 0ull;
                #pragma unroll
                for (int o = 4; o > 0; o >>= 1) {
                    unsigned long long ok = __shfl_down_sync(0xFFFFFFFFu, b2, o);
                    if (ok > b2) b2 = ok;
                }
                if (lane == 0) atomicMax(&g_best[it + 1][grp], b2);
            }
        }
        gsync_grp(grp);
    }
}

// ---------------- launch ----------------
extern "C" void kernel_launch(void* const* d_in, const int* in_sizes, int n_in,
                              void* d_out, int out_size) {
    const float* x = (const float*)d_in[0];
    const float* d = (const float*)d_in[1];
    float* out = (float*)d_out;

    cudaFuncSetAttribute(k_conv_full, cudaFuncAttributeMaxDynamicSharedMemorySize, CONV_SMEM);
    cudaFuncSetAttribute(k_loop,      cudaFuncAttributeMaxDynamicSharedMemorySize, LOOP_SMEM);

    k_norm<<<NATOMS, 256>>>(d);
    {
        int n = BATCH * T_LEN;
        k_init_out<<<(n + 255) / 256, 256>>>(x, out);
    }
    k_conv_full<<<dim3(T_LEN / TNP, NATOMS / TM, BATCH), 256, CONV_SMEM>>>(x);
    k_bmax_init<<<dim3(NBLK, NATOMS, BATCH), 256>>>();
    k_loop<<<PCTAS, 256, LOOP_SMEM>>>(out);
}

// round 13
// speedup vs baseline: 1.1265x; 1.1265x over previous
#include <cuda_runtime.h>
#include <math.h>
#include <cstdint>

#define T_LEN   16384
#define NATOMS  512
#define ALEN    512
#define BATCH   8
#define NBLK    16
#define BLKSZ   1024
#define SIGL    1536
#define N_ITER  32
#define EPS_N   1e-8f

// full-conv tiling: TM_C=64 rows, TNP=128 cols, 2 CTAs/SM
#define TM_C 64
#define KC 64
#define NCHUNK (ALEN / KC)
#define APAD 68
#define TNP 128
#define NI  (TNP / 32)
#define SWIN (TNP + ALEN)
#define SSTR (SWIN + 8)
#define CONV_SMEM ((4 * TM_C * APAD + 2 * SSTR) * 4)     // 74816
// loop kernel
#define KSTR 516
#define SSL  1544
#define LOOP_SMEM ((2 * 32 * KSTR + 2 * SSL) * 4)        // 144448
#define PCTAS 128
#define GRPSZ 16

// ---------------- device-global scratch ----------------
__device__ float g_dn[NATOMS * ALEN];
__device__ __align__(16) uint32_t g_dtf[2 * NATOMS * ALEN];
__device__ float g_fm[(size_t)BATCH * NATOMS * T_LEN];        // 256 MB
__device__ float g_bmax[BATCH * NATOMS * NBLK];
__device__ int   g_barg[BATCH * NATOMS * NBLK];
__device__ unsigned long long g_best[2][BATCH] = {{0}};
__device__ unsigned g_cnt8[BATCH] = {0};
__device__ unsigned g_gen8[BATCH] = {0};

// ---------------- helpers ----------------
__device__ __forceinline__ uint32_t f2tf32(float v) {
    uint32_t r;
    asm("cvt.rna.tf32.f32 %0, %1;" : "=r"(r) : "f"(v));
    return r;
}
__device__ __forceinline__ void mma8(float* c, const uint32_t* a, const uint32_t* b) {
    asm volatile(
        "mma.sync.aligned.m16n8k8.row.col.f32.tf32.tf32.f32 "
        "{%0,%1,%2,%3}, {%4,%5,%6,%7}, {%8,%9}, {%0,%1,%2,%3};"
        : "+f"(c[0]), "+f"(c[1]), "+f"(c[2]), "+f"(c[3])
        : "r"(a[0]), "r"(a[1]), "r"(a[2]), "r"(a[3]), "r"(b[0]), "r"(b[1]));
}
#define CP_COMMIT() asm volatile("cp.async.commit_group;" ::: "memory")
#define CP_WAIT0()  asm volatile("cp.async.wait_group 0;" ::: "memory")
#define CP_WAIT1()  asm volatile("cp.async.wait_group 1;" ::: "memory")

// monotonic float->uint key; low word = 0xFFFFFFFF - flat (first-on-tie via max)
__device__ __forceinline__ unsigned long long pack_key(float v, unsigned flat) {
    unsigned u = __float_as_uint(v);
    unsigned key = (u & 0x80000000u) ? ~u : (u | 0x80000000u);
    return ((unsigned long long)key << 32) | (0xFFFFFFFFu - flat);
}

// conv dict-chunk staging (TM_C rows)
__device__ __forceinline__ void stage_chunk_conv(uint32_t* sAbuf, int n0, int a0, int tid) {
    #pragma unroll
    for (int e = tid; e < TM_C * 16; e += 256) {
        int kq = e & 15, n = e >> 4;
        size_t gi = (size_t)(n0 + n) * ALEN + a0 + kq * 4;
        uint32_t d0 = (uint32_t)__cvta_generic_to_shared(&sAbuf[n * APAD + kq * 4]);
        uint32_t d1 = (uint32_t)__cvta_generic_to_shared(&sAbuf[TM_C * APAD + n * APAD + kq * 4]);
        asm volatile("cp.async.cg.shared.global [%0], [%1], 16;" :: "r"(d0), "l"(&g_dtf[gi]) : "memory");
        asm volatile("cp.async.cg.shared.global [%0], [%1], 16;" :: "r"(d1), "l"(&g_dtf[NATOMS * ALEN + gi]) : "memory");
    }
}

// group-local barrier
__device__ __forceinline__ void gsync_grp(int grp) {
    __syncthreads();
    if (threadIdx.x == 0) {
        unsigned gen = atomicAdd(&g_gen8[grp], 0u);
        __threadfence();
        if (atomicInc(&g_cnt8[grp], GRPSZ - 1) == GRPSZ - 1) {
            atomicAdd(&g_gen8[grp], 1u);
        } else {
            while (atomicAdd(&g_gen8[grp], 0u) == gen) __nanosleep(32);
        }
        __threadfence();
    }
    __syncthreads();
}

// ---------------- setup ----------------
__global__ void k_norm(const float* __restrict__ d) {
    int n = blockIdx.x;
    int tid = threadIdx.x;
    __shared__ float red[256];
    float s = 0.f;
    for (int a = tid; a < ALEN; a += 256) { float v = d[n * ALEN + a]; s += v * v; }
    red[tid] = s; __syncthreads();
    for (int st = 128; st > 0; st >>= 1) {
        if (tid < st) red[tid] += red[tid + st];
        __syncthreads();
    }
    float inv = 1.0f / (sqrtf(red[0]) + EPS_N);
    for (int a = tid; a < ALEN; a += 256) {
        float v = d[n * ALEN + a] * inv;
        g_dn[n * ALEN + a] = v;
        uint32_t big = f2tf32(v);
        g_dtf[n * ALEN + a] = big;
        g_dtf[NATOMS * ALEN + n * ALEN + a] = f2tf32(v - __uint_as_float(big));
    }
}

__global__ void k_init_out(const float* __restrict__ x, float* __restrict__ out) {
    int i = blockIdx.x * blockDim.x + threadIdx.x;
    int n = BATCH * T_LEN;
    if (i < n) { out[i] = x[i]; out[n + i] = 0.f; }
}

// ---------------- full correlation (3xTF32, double-buffered, 2 CTAs/SM) ----------------
__global__ __launch_bounds__(256, 2) void k_conv_full(const float* __restrict__ x) {
    extern __shared__ __align__(16) uint32_t sm[];
    uint32_t* sA = sm;                          // [2 bufs][2 splits][TM_C][APAD]
    uint32_t* sS = sm + 4 * TM_C * APAD;        // [2 splits][SSTR]

    const int b  = blockIdx.z;
    const int n0 = blockIdx.y * TM_C;
    const int t0 = blockIdx.x * TNP;
    const int tid = threadIdx.x;
    const int lane = tid & 31;
    const int wm = (tid >> 5) & 1;              // 2 groups of 32 rows
    const int wn = tid >> 6;                    // 4 groups of 32 cols
    const int g = lane >> 2;
    const int tig = lane & 3;

    const float* sig = x + (size_t)b * T_LEN;

    stage_chunk_conv(sA, n0, 0, tid);
    CP_COMMIT();

    for (int i = tid; i < SWIN; i += 256) {
        int gi = t0 + i;
        float v = (gi < T_LEN) ? sig[gi] : 0.f;
        uint32_t big = f2tf32(v);
        sS[i] = big;
        sS[SSTR + i] = f2tf32(v - __uint_as_float(big));
    }

    float acc[2][NI][4];
    #pragma unroll
    for (int mi = 0; mi < 2; mi++)
        #pragma unroll
        for (int ni = 0; ni < NI; ni++)
            #pragma unroll
            for (int q = 0; q < 4; q++) acc[mi][ni][q] = 0.f;

    for (int i = 0; i < NCHUNK; i++) {
        if (i + 1 < NCHUNK) {
            stage_chunk_conv(sA + ((i + 1) & 1) * 2 * TM_C * APAD, n0, (i + 1) * KC, tid);
            CP_COMMIT();
            CP_WAIT1();
        } else {
            CP_WAIT0();
        }
        __syncthreads();
        const uint32_t* base = sA + (i & 1) * 2 * TM_C * APAD;
        const int a0 = i * KC;

        #pragma unroll
        for (int kk = 0; kk < KC / 8; kk++) {
            const int col = kk * 8 + tig;
            uint32_t Ab[2][4], As[2][4], Bb[NI][2], Bs[NI][2];
            #pragma unroll
            for (int mi = 0; mi < 2; mi++) {
                int rm = wm * 32 + mi * 16 + g;
                const uint32_t* p = &base[rm * APAD + col];
                Ab[mi][0] = p[0];
                Ab[mi][1] = p[8 * APAD];
                Ab[mi][2] = p[4];
                Ab[mi][3] = p[8 * APAD + 4];
                const uint32_t* q = p + TM_C * APAD;
                As[mi][0] = q[0];
                As[mi][1] = q[8 * APAD];
                As[mi][2] = q[4];
                As[mi][3] = q[8 * APAD + 4];
            }
            #pragma unroll
            for (int ni = 0; ni < NI; ni++) {
                int idx = wn * (TNP / 4) + ni * 8 + g + a0 + col;
                Bb[ni][0] = sS[idx];
                Bb[ni][1] = sS[idx + 4];
                Bs[ni][0] = sS[SSTR + idx];
                Bs[ni][1] = sS[SSTR + idx + 4];
            }
            #pragma unroll
            for (int mi = 0; mi < 2; mi++)
                #pragma unroll
                for (int ni = 0; ni < NI; ni++) {
                    mma8(acc[mi][ni], As[mi], Bb[ni]);
                    mma8(acc[mi][ni], Ab[mi], Bs[ni]);
                    mma8(acc[mi][ni], Ab[mi], Bb[ni]);
                }
        }
        __syncthreads();
    }

    #pragma unroll
    for (int mi = 0; mi < 2; mi++) {
        int n1 = n0 + wm * 32 + mi * 16 + g;
        float* row1 = g_fm + ((size_t)(b * NATOMS + n1)) * T_LEN;
        float* row2 = row1 + 8 * (size_t)T_LEN;
        #pragma unroll
        for (int ni = 0; ni < NI; ni++) {
            int tc = t0 + wn * (TNP / 4) + ni * 8 + tig * 2;
            *(float2*)(row1 + tc) = make_float2(acc[mi][ni][0], acc[mi][ni][1]);
            *(float2*)(row2 + tc) = make_float2(acc[mi][ni][2], acc[mi][ni][3]);
        }
    }
}

// ---------------- initial block-max ----------------
__global__ __launch_bounds__(256) void k_bmax_init() {
    int b = blockIdx.z, n = blockIdx.y, bl = blockIdx.x;
    const float* row = &g_fm[((size_t)(b * NATOMS + n)) * T_LEN + bl * BLKSZ];
    int tid = threadIdx.x;
    float4 v = *reinterpret_cast<const float4*>(&row[tid * 4]);
    float bv = v.x; int bt = tid * 4;
    if (v.y > bv) { bv = v.y; bt = tid * 4 + 1; }
    if (v.z > bv) { bv = v.z; bt = tid * 4 + 2; }
    if (v.w > bv) { bv = v.w; bt = tid * 4 + 3; }
    __shared__ float sv[256];
    __shared__ int   st[256];
    sv[tid] = bv; st[tid] = bt;
    __syncthreads();
    for (int s = 128; s > 0; s >>= 1) {
        if (tid < s) {
            if (sv[tid + s] > sv[tid] || (sv[tid + s] == sv[tid] && st[tid + s] < st[tid])) {
                sv[tid] = sv[tid + s]; st[tid] = st[tid + s];
            }
        }
        __syncthreads();
    }
    if (tid == 0) {
        int idx = (b * NATOMS + n) * NBLK + bl;
        g_bmax[idx] = sv[0];
        g_barg[idx] = bl * BLKSZ + st[0];
    }
}

// ---------------- persistent loop (round-10 proven version, verbatim) ----------------
__global__ __launch_bounds__(256, 1) void k_loop(float* __restrict__ out) {
    extern __shared__ __align__(16) uint32_t sm[];
    uint32_t* sA = sm;                    // [2 splits][32 n][KSTR]
    uint32_t* sS = sm + 2 * 32 * KSTR;    // [2 splits][SSL]
    __shared__ unsigned long long s_part[8];
    __shared__ unsigned long long s_best;

    const int grp = blockIdx.x >> 4;
    const int mem = blockIdx.x & 15;
    const int n0 = mem * 32;
    const int tid = threadIdx.x;
    const int wid = tid >> 5;
    const int lane = tid & 31;
    const int g = lane >> 2;
    const int tig = lane & 3;

    // stage dictionary slice once
    for (int e = tid; e < 2 * 32 * 128; e += 256) {
        int sp = e >> 12;
        int r  = (e >> 7) & 31;
        int kq = e & 127;
        size_t gi = (size_t)sp * NATOMS * ALEN + (size_t)(n0 + r) * ALEN + kq * 4;
        uint32_t dst = (uint32_t)__cvta_generic_to_shared(&sA[sp * 32 * KSTR + r * KSTR + kq * 4]);
        asm volatile("cp.async.cg.shared.global [%0], [%1], 16;" :: "r"(dst), "l"(&g_dtf[gi]) : "memory");
    }
    CP_COMMIT(); CP_WAIT0();
    __syncthreads();

    for (int it = 0; it < N_ITER; it++) {
        // ---- A-scan: this CTA's 512 (bmax,barg) entries -> one atomicMax ----
        {
            int base = (grp * NATOMS + n0) * NBLK;
            unsigned long long best = 0ull;
            #pragma unroll
            for (int r = 0; r < 2; r++) {
                int e = tid + r * 256;
                float v = g_bmax[base + e];
                unsigned flat = (unsigned)((n0 + (e >> 4)) * T_LEN + g_barg[base + e]);
                unsigned long long k = pack_key(v, flat);
                if (k > best) best = k;
            }
            #pragma unroll
            for (int o = 16; o > 0; o >>= 1) {
                unsigned long long ok = __shfl_down_sync(0xFFFFFFFFu, best, o);
                if (ok > best) best = ok;
            }
            if (lane == 0) s_part[wid] = best;
            __syncthreads();
            if (wid == 0) {
                unsigned long long b2 = (lane < 8) ? s_part[lane] : 0ull;
                #pragma unroll
                for (int o = 4; o > 0; o >>= 1) {
                    unsigned long long ok = __shfl_down_sync(0xFFFFFFFFu, b2, o);
                    if (ok > b2) b2 = ok;
                }
                if (lane == 0) atomicMax(&g_best[it & 1][grp], b2);
            }
        }
        gsync_grp(grp);

        // ---- decode winner ----
        if (tid == 0) s_best = *((volatile unsigned long long*)&g_best[it & 1][grp]);
        __syncthreads();
        unsigned long long w = s_best;
        unsigned key = (unsigned)(w >> 32);
        unsigned uv = (key & 0x80000000u) ? (key & 0x7FFFFFFFu) : ~key;
        float v = __uint_as_float(uv);
        unsigned flat = 0xFFFFFFFFu - (unsigned)(w & 0xFFFFFFFFu);
        int n = (int)(flat >> 14);
        int t = (int)(flat & (T_LEN - 1));
        int L = min(t + ALEN, T_LEN - 1) - t;   // ref clips: position T-1 never written

        if (mem == 0) {
            // residual/recon update + reset idle-parity slot
            if (tid == 0) *((volatile unsigned long long*)&g_best[(it + 1) & 1][grp]) = 0ull;
            float* res = out + (size_t)grp * T_LEN;
            float* rec = out + (size_t)(BATCH + grp) * T_LEN;
            for (int u = tid; u < L; u += 256) {
                float wv = v * g_dn[n * ALEN + u];
                res[t + u] -= wv;
                rec[t + u] += wv;
            }
        }
        if (it == N_ITER - 1) return;

        if (L > 0) {
            int toff = t - (ALEN - 1);
            // build tf32 splits of the delta signal directly from g_dn
            for (int i = tid; i < SIGL; i += 256) {
                int j = i - (ALEN - 1);
                float sv = (j >= 0 && j < L) ? v * g_dn[n * ALEN + j] : 0.f;
                uint32_t big = f2tf32(sv);
                sS[i] = big;
                sS[SSL + i] = f2tf32(sv - __uint_as_float(big));
            }
            __syncthreads();

            #pragma unroll
            for (int pass = 0; pass < 2; pass++) {
                int tw = pass * 512 + wid * 64;
                int klo = max(0, (ALEN - 1) - (tw + 63)) & ~7;
                int khi = min(ALEN, (ALEN - 1) + L - tw);
                khi = (khi + 7) & ~7;
                if (klo >= khi) continue;

                float acc[2][8][4];
                #pragma unroll
                for (int mi = 0; mi < 2; mi++)
                    #pragma unroll
                    for (int ni = 0; ni < 8; ni++)
                        #pragma unroll
                        for (int q = 0; q < 4; q++) acc[mi][ni][q] = 0.f;

                for (int k0 = klo; k0 < khi; k0 += 8) {
                    int col = k0 + tig;
                    uint32_t Ab[2][4], As[2][4], Bb[8][2], Bs[8][2];
                    #pragma unroll
                    for (int mi = 0; mi < 2; mi++) {
                        const uint32_t* p = &sA[(mi * 16 + g) * KSTR + col];
                        Ab[mi][0] = p[0];
                        Ab[mi][1] = p[8 * KSTR];
                        Ab[mi][2] = p[4];
                        Ab[mi][3] = p[8 * KSTR + 4];
                        const uint32_t* q = p + 32 * KSTR;
                        As[mi][0] = q[0];
                        As[mi][1] = q[8 * KSTR];
                        As[mi][2] = q[4];
                        As[mi][3] = q[8 * KSTR + 4];
                    }
                    #pragma unroll
                    for (int ni = 0; ni < 8; ni++) {
                        int idx = tw + ni * 8 + g + col;
                        Bb[ni][0] = sS[idx];
                        Bb[ni][1] = sS[idx + 4];
                        Bs[ni][0] = sS[SSL + idx];
                        Bs[ni][1] = sS[SSL + idx + 4];
                    }
                    #pragma unroll
                    for (int mi = 0; mi < 2; mi++)
                        #pragma unroll
                        for (int ni = 0; ni < 8; ni++) {
                            mma8(acc[mi][ni], As[mi], Bb[ni]);
                            mma8(acc[mi][ni], Ab[mi], Bs[ni]);
                            mma8(acc[mi][ni], Ab[mi], Bb[ni]);
                        }
                }

                #pragma unroll
                for (int mi = 0; mi < 2; mi++) {
                    int n1 = n0 + mi * 16 + g;
                    float* row1 = g_fm + ((size_t)(grp * NATOMS + n1)) * T_LEN;
                    float* row2 = row1 + 8 * (size_t)T_LEN;
                    #pragma unroll
                    for (int ni = 0; ni < 8; ni++) {
                        int tt = toff + tw + ni * 8 + tig * 2;
                        if (tt >= 0 && tt < T_LEN)         row1[tt]     -= acc[mi][ni][0];
                        if (tt + 1 >= 0 && tt + 1 < T_LEN) row1[tt + 1] -= acc[mi][ni][1];
                        if (tt >= 0 && tt < T_LEN)         row2[tt]     -= acc[mi][ni][2];
                        if (tt + 1 >= 0 && tt + 1 < T_LEN) row2[tt + 1] -= acc[mi][ni][3];
                    }
                }
            }
            __syncthreads();   // all delta stores visible CTA-wide before refresh reads

            // ---- refresh own rows' touched block maxima (CTA-local fm) ----
            {
                int lo = max(0, t - (ALEN - 1));
                int hi = min(T_LEN - 1, t + (ALEN - 1));
                int bl0 = lo >> 10, bl1 = hi >> 10;
                for (int u = wid; u < 64; u += 8) {
                    int r = u >> 1;
                    int which = u & 1;
                    if (which && bl1 == bl0) continue;
                    int bl = which ? bl1 : bl0;
                    const float* row = &g_fm[((size_t)(grp * NATOMS + n0 + r)) * T_LEN + bl * BLKSZ];
                    float bv = -3.402823466e38f;
                    int bt = 0x7FFFFFFF;
                    #pragma unroll
                    for (int i = 0; i < 8; i++) {
                        int base = (i * 32 + lane) * 4;
                        float4 vv = *(const float4*)&row[base];
                        if (vv.x > bv) { bv = vv.x; bt = base; }
                        if (vv.y > bv) { bv = vv.y; bt = base + 1; }
                        if (vv.z > bv) { bv = vv.z; bt = base + 2; }
                        if (vv.w > bv) { bv = vv.w; bt = base + 3; }
                    }
                    #pragma unroll
                    for (int o = 16; o > 0; o >>= 1) {
                        float ov = __shfl_down_sync(0xFFFFFFFFu, bv, o);
                        int   ot = __shfl_down_sync(0xFFFFFFFFu, bt, o);
                        if (ov > bv || (ov == bv && ot < bt)) { bv = ov; bt = ot; }
                    }
                    if (lane == 0) {
                        int idx = (grp * NATOMS + n0 + r) * NBLK + bl;
                        g_bmax[idx] = bv;
                        g_barg[idx] = bl * BLKSZ + bt;
                    }
                }
            }
        }
        gsync_grp(grp);
    }
}

// ---------------- launch ----------------
extern "C" void kernel_launch(void* const* d_in, const int* in_sizes, int n_in,
                              void* d_out, int out_size) {
    const float* x = (const float*)d_in[0];
    const float* d = (const float*)d_in[1];
    float* out = (float*)d_out;

    cudaFuncSetAttribute(k_conv_full, cudaFuncAttributeMaxDynamicSharedMemorySize, CONV_SMEM);
    cudaFuncSetAttribute(k_loop,      cudaFuncAttributeMaxDynamicSharedMemorySize, LOOP_SMEM);

    k_norm<<<NATOMS, 256>>>(d);
    {
        int n = BATCH * T_LEN;
        k_init_out<<<(n + 255) / 256, 256>>>(x, out);
    }
    k_conv_full<<<dim3(T_LEN / TNP, NATOMS / TM_C, BATCH), 256, CONV_SMEM>>>(x);
    k_bmax_init<<<dim3(NBLK, NATOMS, BATCH), 256>>>();
    k_loop<<<PCTAS, 256, LOOP_SMEM>>>(out);
}

// round 14
// speedup vs baseline: 1.3300x; 1.1806x over previous
#include <cuda_runtime.h>
#include <math.h>
#include <cstdint>

#define T_LEN   16384
#define NATOMS  512
#define ALEN    512
#define BATCH   8
#define NBLK    16
#define BLKSZ   1024
#define SIGL    1536
#define N_ITER  32
#define EPS_N   1e-8f

// full-conv tiling: TM_C=64 rows, TNP=128 cols, 2 CTAs/SM (round-13 proven)
#define TM_C 64
#define KC 64
#define NCHUNK (ALEN / KC)
#define APAD 68
#define TNP 128
#define NI  (TNP / 32)
#define SWIN (TNP + ALEN)
#define SSTR (SWIN + 8)
#define CONV_SMEM ((4 * TM_C * APAD + 2 * SSTR) * 4)     // 74816
// loop kernel: 16-atom slices, 2 CTAs/SM
#define KSTR 516
#define SSL  1544
#define LOOP_SMEM ((2 * 16 * KSTR + 2 * SSL) * 4)        // 78400
#define PCTAS 256
#define GRPSZ 32

// ---------------- device-global scratch ----------------
__device__ float g_dn[NATOMS * ALEN];
__device__ __align__(16) uint32_t g_dtf[2 * NATOMS * ALEN];
__device__ float g_fm[(size_t)BATCH * NATOMS * T_LEN];        // 256 MB
__device__ float g_bmax[BATCH * NATOMS * NBLK];
__device__ int   g_barg[BATCH * NATOMS * NBLK];
__device__ unsigned long long g_best[2][BATCH] = {{0}};
__device__ unsigned g_cnt8[BATCH] = {0};
__device__ unsigned g_gen8[BATCH] = {0};

// ---------------- helpers ----------------
__device__ __forceinline__ uint32_t f2tf32(float v) {
    uint32_t r;
    asm("cvt.rna.tf32.f32 %0, %1;" : "=r"(r) : "f"(v));
    return r;
}
__device__ __forceinline__ void mma8(float* c, const uint32_t* a, const uint32_t* b) {
    asm volatile(
        "mma.sync.aligned.m16n8k8.row.col.f32.tf32.tf32.f32 "
        "{%0,%1,%2,%3}, {%4,%5,%6,%7}, {%8,%9}, {%0,%1,%2,%3};"
        : "+f"(c[0]), "+f"(c[1]), "+f"(c[2]), "+f"(c[3])
        : "r"(a[0]), "r"(a[1]), "r"(a[2]), "r"(a[3]), "r"(b[0]), "r"(b[1]));
}
#define CP_COMMIT() asm volatile("cp.async.commit_group;" ::: "memory")
#define CP_WAIT0()  asm volatile("cp.async.wait_group 0;" ::: "memory")
#define CP_WAIT1()  asm volatile("cp.async.wait_group 1;" ::: "memory")

// monotonic float->uint key; low word = 0xFFFFFFFF - flat (first-on-tie via max)
__device__ __forceinline__ unsigned long long pack_key(float v, unsigned flat) {
    unsigned u = __float_as_uint(v);
    unsigned key = (u & 0x80000000u) ? ~u : (u | 0x80000000u);
    return ((unsigned long long)key << 32) | (0xFFFFFFFFu - flat);
}

// conv dict-chunk staging (TM_C rows)
__device__ __forceinline__ void stage_chunk_conv(uint32_t* sAbuf, int n0, int a0, int tid) {
    #pragma unroll
    for (int e = tid; e < TM_C * 16; e += 256) {
        int kq = e & 15, n = e >> 4;
        size_t gi = (size_t)(n0 + n) * ALEN + a0 + kq * 4;
        uint32_t d0 = (uint32_t)__cvta_generic_to_shared(&sAbuf[n * APAD + kq * 4]);
        uint32_t d1 = (uint32_t)__cvta_generic_to_shared(&sAbuf[TM_C * APAD + n * APAD + kq * 4]);
        asm volatile("cp.async.cg.shared.global [%0], [%1], 16;" :: "r"(d0), "l"(&g_dtf[gi]) : "memory");
        asm volatile("cp.async.cg.shared.global [%0], [%1], 16;" :: "r"(d1), "l"(&g_dtf[NATOMS * ALEN + gi]) : "memory");
    }
}

// group-local barrier (GRPSZ co-resident CTAs of one batch)
__device__ __forceinline__ void gsync_grp(int grp) {
    __syncthreads();
    if (threadIdx.x == 0) {
        unsigned gen = atomicAdd(&g_gen8[grp], 0u);
        __threadfence();
        if (atomicInc(&g_cnt8[grp], GRPSZ - 1) == GRPSZ - 1) {
            atomicAdd(&g_gen8[grp], 1u);
        } else {
            while (atomicAdd(&g_gen8[grp], 0u) == gen) __nanosleep(32);
        }
        __threadfence();
    }
    __syncthreads();
}

// ---------------- setup ----------------
__global__ void k_norm(const float* __restrict__ d) {
    int n = blockIdx.x;
    int tid = threadIdx.x;
    __shared__ float red[256];
    float s = 0.f;
    for (int a = tid; a < ALEN; a += 256) { float v = d[n * ALEN + a]; s += v * v; }
    red[tid] = s; __syncthreads();
    for (int st = 128; st > 0; st >>= 1) {
        if (tid < st) red[tid] += red[tid + st];
        __syncthreads();
    }
    float inv = 1.0f / (sqrtf(red[0]) + EPS_N);
    for (int a = tid; a < ALEN; a += 256) {
        float v = d[n * ALEN + a] * inv;
        g_dn[n * ALEN + a] = v;
        uint32_t big = f2tf32(v);
        g_dtf[n * ALEN + a] = big;
        g_dtf[NATOMS * ALEN + n * ALEN + a] = f2tf32(v - __uint_as_float(big));
    }
}

__global__ void k_init_out(const float* __restrict__ x, float* __restrict__ out) {
    int i = blockIdx.x * blockDim.x + threadIdx.x;
    int n = BATCH * T_LEN;
    if (i < n) { out[i] = x[i]; out[n + i] = 0.f; }
}

// ---------------- full correlation (3xTF32, double-buffered, 2 CTAs/SM) ----------------
__global__ __launch_bounds__(256, 2) void k_conv_full(const float* __restrict__ x) {
    extern __shared__ __align__(16) uint32_t sm[];
    uint32_t* sA = sm;
    uint32_t* sS = sm + 4 * TM_C * APAD;

    const int b  = blockIdx.z;
    const int n0 = blockIdx.y * TM_C;
    const int t0 = blockIdx.x * TNP;
    const int tid = threadIdx.x;
    const int lane = tid & 31;
    const int wm = (tid >> 5) & 1;
    const int wn = tid >> 6;
    const int g = lane >> 2;
    const int tig = lane & 3;

    const float* sig = x + (size_t)b * T_LEN;

    stage_chunk_conv(sA, n0, 0, tid);
    CP_COMMIT();

    for (int i = tid; i < SWIN; i += 256) {
        int gi = t0 + i;
        float v = (gi < T_LEN) ? sig[gi] : 0.f;
        uint32_t big = f2tf32(v);
        sS[i] = big;
        sS[SSTR + i] = f2tf32(v - __uint_as_float(big));
    }

    float acc[2][NI][4];
    #pragma unroll
    for (int mi = 0; mi < 2; mi++)
        #pragma unroll
        for (int ni = 0; ni < NI; ni++)
            #pragma unroll
            for (int q = 0; q < 4; q++) acc[mi][ni][q] = 0.f;

    for (int i = 0; i < NCHUNK; i++) {
        if (i + 1 < NCHUNK) {
            stage_chunk_conv(sA + ((i + 1) & 1) * 2 * TM_C * APAD, n0, (i + 1) * KC, tid);
            CP_COMMIT();
            CP_WAIT1();
        } else {
            CP_WAIT0();
        }
        __syncthreads();
        const uint32_t* base = sA + (i & 1) * 2 * TM_C * APAD;
        const int a0 = i * KC;

        #pragma unroll
        for (int kk = 0; kk < KC / 8; kk++) {
            const int col = kk * 8 + tig;
            uint32_t Ab[2][4], As[2][4], Bb[NI][2], Bs[NI][2];
            #pragma unroll
            for (int mi = 0; mi < 2; mi++) {
                int rm = wm * 32 + mi * 16 + g;
                const uint32_t* p = &base[rm * APAD + col];
                Ab[mi][0] = p[0];
                Ab[mi][1] = p[8 * APAD];
                Ab[mi][2] = p[4];
                Ab[mi][3] = p[8 * APAD + 4];
                const uint32_t* q = p + TM_C * APAD;
                As[mi][0] = q[0];
                As[mi][1] = q[8 * APAD];
                As[mi][2] = q[4];
                As[mi][3] = q[8 * APAD + 4];
            }
            #pragma unroll
            for (int ni = 0; ni < NI; ni++) {
                int idx = wn * (TNP / 4) + ni * 8 + g + a0 + col;
                Bb[ni][0] = sS[idx];
                Bb[ni][1] = sS[idx + 4];
                Bs[ni][0] = sS[SSTR + idx];
                Bs[ni][1] = sS[SSTR + idx + 4];
            }
            #pragma unroll
            for (int mi = 0; mi < 2; mi++)
                #pragma unroll
                for (int ni = 0; ni < NI; ni++) {
                    mma8(acc[mi][ni], As[mi], Bb[ni]);
                    mma8(acc[mi][ni], Ab[mi], Bs[ni]);
                    mma8(acc[mi][ni], Ab[mi], Bb[ni]);
                }
        }
        __syncthreads();
    }

    #pragma unroll
    for (int mi = 0; mi < 2; mi++) {
        int n1 = n0 + wm * 32 + mi * 16 + g;
        float* row1 = g_fm + ((size_t)(b * NATOMS + n1)) * T_LEN;
        float* row2 = row1 + 8 * (size_t)T_LEN;
        #pragma unroll
        for (int ni = 0; ni < NI; ni++) {
            int tc = t0 + wn * (TNP / 4) + ni * 8 + tig * 2;
            *(float2*)(row1 + tc) = make_float2(acc[mi][ni][0], acc[mi][ni][1]);
            *(float2*)(row2 + tc) = make_float2(acc[mi][ni][2], acc[mi][ni][3]);
        }
    }
}

// ---------------- initial block-max ----------------
__global__ __launch_bounds__(256) void k_bmax_init() {
    int b = blockIdx.z, n = blockIdx.y, bl = blockIdx.x;
    const float* row = &g_fm[((size_t)(b * NATOMS + n)) * T_LEN + bl * BLKSZ];
    int tid = threadIdx.x;
    float4 v = *reinterpret_cast<const float4*>(&row[tid * 4]);
    float bv = v.x; int bt = tid * 4;
    if (v.y > bv) { bv = v.y; bt = tid * 4 + 1; }
    if (v.z > bv) { bv = v.z; bt = tid * 4 + 2; }
    if (v.w > bv) { bv = v.w; bt = tid * 4 + 3; }
    __shared__ float sv[256];
    __shared__ int   st[256];
    sv[tid] = bv; st[tid] = bt;
    __syncthreads();
    for (int s = 128; s > 0; s >>= 1) {
        if (tid < s) {
            if (sv[tid + s] > sv[tid] || (sv[tid + s] == sv[tid] && st[tid + s] < st[tid])) {
                sv[tid] = sv[tid + s]; st[tid] = st[tid + s];
            }
        }
        __syncthreads();
    }
    if (tid == 0) {
        int idx = (b * NATOMS + n) * NBLK + bl;
        g_bmax[idx] = sv[0];
        g_barg[idx] = bl * BLKSZ + st[0];
    }
}

// ---------------- persistent loop: 16-atom slices, 2 CTAs/SM ----------------
__global__ __launch_bounds__(256, 2) void k_loop(float* __restrict__ out) {
    extern __shared__ __align__(16) uint32_t sm[];
    uint32_t* sA = sm;                    // [2 splits][16 n][KSTR]
    uint32_t* sS = sm + 2 * 16 * KSTR;    // [2 splits][SSL]
    __shared__ unsigned long long s_part[8];
    __shared__ unsigned long long s_best;

    const int grp = blockIdx.x >> 5;      // batch
    const int mem = blockIdx.x & 31;      // 16-atom slice
    const int n0 = mem * 16;
    const int tid = threadIdx.x;
    const int wid = tid >> 5;
    const int lane = tid & 31;
    const int g = lane >> 2;
    const int tig = lane & 3;

    // stage dictionary slice once (2 splits x 16 rows x 512 K)
    for (int e = tid; e < 2 * 16 * 128; e += 256) {
        int sp = e >> 11;
        int r  = (e >> 7) & 15;
        int kq = e & 127;
        size_t gi = (size_t)sp * NATOMS * ALEN + (size_t)(n0 + r) * ALEN + kq * 4;
        uint32_t dst = (uint32_t)__cvta_generic_to_shared(&sA[sp * 16 * KSTR + r * KSTR + kq * 4]);
        asm volatile("cp.async.cg.shared.global [%0], [%1], 16;" :: "r"(dst), "l"(&g_dtf[gi]) : "memory");
    }
    CP_COMMIT(); CP_WAIT0();
    __syncthreads();

    for (int it = 0; it < N_ITER; it++) {
        // ---- A-scan: this CTA's 256 (bmax,barg) entries (1/thread) -> one atomicMax ----
        {
            int base = (grp * NATOMS + n0) * NBLK;
            float v = g_bmax[base + tid];
            unsigned flat = (unsigned)((n0 + (tid >> 4)) * T_LEN + g_barg[base + tid]);
            unsigned long long best = pack_key(v, flat);
            #pragma unroll
            for (int o = 16; o > 0; o >>= 1) {
                unsigned long long ok = __shfl_down_sync(0xFFFFFFFFu, best, o);
                if (ok > best) best = ok;
            }
            if (lane == 0) s_part[wid] = best;
            __syncthreads();
            if (wid == 0) {
                unsigned long long b2 = (lane < 8) ? s_part[lane] : 0ull;
                #pragma unroll
                for (int o = 4; o > 0; o >>= 1) {
                    unsigned long long ok = __shfl_down_sync(0xFFFFFFFFu, b2, o);
                    if (ok > b2) b2 = ok;
                }
                if (lane == 0) atomicMax(&g_best[it & 1][grp], b2);
            }
        }
        gsync_grp(grp);

        // ---- decode winner ----
        if (tid == 0) s_best = *((volatile unsigned long long*)&g_best[it & 1][grp]);
        __syncthreads();
        unsigned long long w = s_best;
        unsigned key = (unsigned)(w >> 32);
        unsigned uv = (key & 0x80000000u) ? (key & 0x7FFFFFFFu) : ~key;
        float v = __uint_as_float(uv);
        unsigned flat = 0xFFFFFFFFu - (unsigned)(w & 0xFFFFFFFFu);
        int n = (int)(flat >> 14);
        int t = (int)(flat & (T_LEN - 1));
        int L = min(t + ALEN, T_LEN - 1) - t;   // ref clips: position T-1 never written

        if (mem == 0) {
            // residual/recon update + reset idle-parity slot
            if (tid == 0) *((volatile unsigned long long*)&g_best[(it + 1) & 1][grp]) = 0ull;
            float* res = out + (size_t)grp * T_LEN;
            float* rec = out + (size_t)(BATCH + grp) * T_LEN;
            for (int u = tid; u < L; u += 256) {
                float wv = v * g_dn[n * ALEN + u];
                res[t + u] -= wv;
                rec[t + u] += wv;
            }
        }
        if (it == N_ITER - 1) return;

        if (L > 0) {
            int toff = t - (ALEN - 1);
            // build tf32 splits of the delta signal directly from g_dn
            for (int i = tid; i < SIGL; i += 256) {
                int j = i - (ALEN - 1);
                float sv = (j >= 0 && j < L) ? v * g_dn[n * ALEN + j] : 0.f;
                uint32_t big = f2tf32(sv);
                sS[i] = big;
                sS[SSL + i] = f2tf32(sv - __uint_as_float(big));
            }
            __syncthreads();

            #pragma unroll
            for (int pass = 0; pass < 2; pass++) {
                int tw = pass * 512 + wid * 64;
                int klo = max(0, (ALEN - 1) - (tw + 63)) & ~7;
                int khi = min(ALEN, (ALEN - 1) + L - tw);
                khi = (khi + 7) & ~7;
                if (klo >= khi) continue;

                float acc[8][4];
                #pragma unroll
                for (int ni = 0; ni < 8; ni++)
                    #pragma unroll
                    for (int q = 0; q < 4; q++) acc[ni][q] = 0.f;

                for (int k0 = klo; k0 < khi; k0 += 8) {
                    int col = k0 + tig;
                    uint32_t Ab[4], As[4], Bb[8][2], Bs[8][2];
                    {
                        const uint32_t* p = &sA[g * KSTR + col];
                        Ab[0] = p[0];
                        Ab[1] = p[8 * KSTR];
                        Ab[2] = p[4];
                        Ab[3] = p[8 * KSTR + 4];
                        const uint32_t* q = p + 16 * KSTR;
                        As[0] = q[0];
                        As[1] = q[8 * KSTR];
                        As[2] = q[4];
                        As[3] = q[8 * KSTR + 4];
                    }
                    #pragma unroll
                    for (int ni = 0; ni < 8; ni++) {
                        int idx = tw + ni * 8 + g + col;
                        Bb[ni][0] = sS[idx];
                        Bb[ni][1] = sS[idx + 4];
                        Bs[ni][0] = sS[SSL + idx];
                        Bs[ni][1] = sS[SSL + idx + 4];
                    }
                    #pragma unroll
                    for (int ni = 0; ni < 8; ni++) {
                        mma8(acc[ni], As, Bb[ni]);
                        mma8(acc[ni], Ab, Bs[ni]);
                        mma8(acc[ni], Ab, Bb[ni]);
                    }
                }

                {
                    int n1 = n0 + g;
                    float* row1 = g_fm + ((size_t)(grp * NATOMS + n1)) * T_LEN;
                    float* row2 = row1 + 8 * (size_t)T_LEN;
                    #pragma unroll
                    for (int ni = 0; ni < 8; ni++) {
                        int tt = toff + tw + ni * 8 + tig * 2;
                        if (tt >= 0 && tt < T_LEN)         row1[tt]     -= acc[ni][0];
                        if (tt + 1 >= 0 && tt + 1 < T_LEN) row1[tt + 1] -= acc[ni][1];
                        if (tt >= 0 && tt < T_LEN)         row2[tt]     -= acc[ni][2];
                        if (tt + 1 >= 0 && tt + 1 < T_LEN) row2[tt + 1] -= acc[ni][3];
                    }
                }
            }
            __syncthreads();   // all delta stores visible CTA-wide before refresh reads

            // ---- refresh own rows' touched block maxima (16 rows x <=2 blocks) ----
            {
                int lo = max(0, t - (ALEN - 1));
                int hi = min(T_LEN - 1, t + (ALEN - 1));
                int bl0 = lo >> 10, bl1 = hi >> 10;
                for (int u = wid; u < 32; u += 8) {
                    int r = u >> 1;
                    int which = u & 1;
                    if (which && bl1 == bl0) continue;
                    int bl = which ? bl1 : bl0;
                    const float* row = &g_fm[((size_t)(grp * NATOMS + n0 + r)) * T_LEN + bl * BLKSZ];
                    float bv = -3.402823466e38f;
                    int bt = 0x7FFFFFFF;
                    #pragma unroll
                    for (int i = 0; i < 8; i++) {
                        int base = (i * 32 + lane) * 4;
                        float4 vv = *(const float4*)&row[base];
                        if (vv.x > bv) { bv = vv.x; bt = base; }
                        if (vv.y > bv) { bv = vv.y; bt = base + 1; }
                        if (vv.z > bv) { bv = vv.z; bt = base + 2; }
                        if (vv.w > bv) { bv = vv.w; bt = base + 3; }
                    }
                    #pragma unroll
                    for (int o = 16; o > 0; o >>= 1) {
                        float ov = __shfl_down_sync(0xFFFFFFFFu, bv, o);
                        int   ot = __shfl_down_sync(0xFFFFFFFFu, bt, o);
                        if (ov > bv || (ov == bv && ot < bt)) { bv = ov; bt = ot; }
                    }
                    if (lane == 0) {
                        int idx = (grp * NATOMS + n0 + r) * NBLK + bl;
                        g_bmax[idx] = bv;
                        g_barg[idx] = bl * BLKSZ + bt;
                    }
                }
            }
        }
        gsync_grp(grp);
    }
}

// ---------------- launch ----------------
extern "C" void kernel_launch(void* const* d_in, const int* in_sizes, int n_in,
                              void* d_out, int out_size) {
    const float* x = (const float*)d_in[0];
    const float* d = (const float*)d_in[1];
    float* out = (float*)d_out;

    cudaFuncSetAttribute(k_conv_full, cudaFuncAttributeMaxDynamicSharedMemorySize, CONV_SMEM);
    cudaFuncSetAttribute(k_loop,      cudaFuncAttributeMaxDynamicSharedMemorySize, LOOP_SMEM);

    k_norm<<<NATOMS, 256>>>(d);
    {
        int n = BATCH * T_LEN;
        k_init_out<<<(n + 255) / 256, 256>>>(x, out);
    }
    k_conv_full<<<dim3(T_LEN / TNP, NATOMS / TM_C, BATCH), 256, CONV_SMEM>>>(x);
    k_bmax_init<<<dim3(NBLK, NATOMS, BATCH), 256>>>();
    k_loop<<<PCTAS, 256, LOOP_SMEM>>>(out);
}

// round 15
// speedup vs baseline: 1.3884x; 1.0439x over previous
#include <cuda_runtime.h>
#include <math.h>
#include <cstdint>

#define T_LEN   16384
#define NATOMS  512
#define ALEN    512
#define BATCH   8
#define NBLK    16
#define BLKSZ   1024
#define SIGL    1536
#define N_ITER  32
#define EPS_N   1e-8f

// full-conv tiling: TM_C=64 rows, TNP=128 cols, 2 CTAs/SM (round-13 proven)
#define TM_C 64
#define KC 64
#define NCHUNK (ALEN / KC)
#define APAD 68
#define TNP 128
#define NI  (TNP / 32)
#define SWIN (TNP + ALEN)
#define SSTR (SWIN + 8)
#define CONV_SMEM ((4 * TM_C * APAD + 2 * SSTR) * 4)     // 74816
// loop kernel: 16-atom slices, 2 CTAs/SM
#define KSTR 516
#define SSL  1544
#define LOOP_SMEM ((2 * 16 * KSTR + 2 * SSL) * 4)        // 78400
#define PCTAS 256
#define GRPSZ 32

// ---------------- device-global scratch ----------------
__device__ float g_dn[NATOMS * ALEN];
__device__ __align__(16) uint32_t g_dtf[2 * NATOMS * ALEN];
__device__ float g_fm[(size_t)BATCH * NATOMS * T_LEN];        // 256 MB
__device__ float g_bmax[BATCH * NATOMS * NBLK];
__device__ int   g_barg[BATCH * NATOMS * NBLK];
__device__ unsigned long long g_best[(N_ITER + 1) * BATCH];
__device__ unsigned g_cnt8[BATCH] = {0};
__device__ unsigned g_gen8[BATCH] = {0};

// ---------------- helpers ----------------
__device__ __forceinline__ uint32_t f2tf32(float v) {
    uint32_t r;
    asm("cvt.rna.tf32.f32 %0, %1;" : "=r"(r) : "f"(v));
    return r;
}
__device__ __forceinline__ void mma8(float* c, const uint32_t* a, const uint32_t* b) {
    asm volatile(
        "mma.sync.aligned.m16n8k8.row.col.f32.tf32.tf32.f32 "
        "{%0,%1,%2,%3}, {%4,%5,%6,%7}, {%8,%9}, {%0,%1,%2,%3};"
        : "+f"(c[0]), "+f"(c[1]), "+f"(c[2]), "+f"(c[3])
        : "r"(a[0]), "r"(a[1]), "r"(a[2]), "r"(a[3]), "r"(b[0]), "r"(b[1]));
}
#define CP_COMMIT() asm volatile("cp.async.commit_group;" ::: "memory")
#define CP_WAIT0()  asm volatile("cp.async.wait_group 0;" ::: "memory")
#define CP_WAIT1()  asm volatile("cp.async.wait_group 1;" ::: "memory")

// monotonic float->uint key; low word = 0xFFFFFFFF - flat (first-on-tie via max)
__device__ __forceinline__ unsigned long long pack_key(float v, unsigned flat) {
    unsigned u = __float_as_uint(v);
    unsigned key = (u & 0x80000000u) ? ~u : (u | 0x80000000u);
    return ((unsigned long long)key << 32) | (0xFFFFFFFFu - flat);
}

// conv dict-chunk staging (TM_C rows)
__device__ __forceinline__ void stage_chunk_conv(uint32_t* sAbuf, int n0, int a0, int tid) {
    #pragma unroll
    for (int e = tid; e < TM_C * 16; e += 256) {
        int kq = e & 15, n = e >> 4;
        size_t gi = (size_t)(n0 + n) * ALEN + a0 + kq * 4;
        uint32_t d0 = (uint32_t)__cvta_generic_to_shared(&sAbuf[n * APAD + kq * 4]);
        uint32_t d1 = (uint32_t)__cvta_generic_to_shared(&sAbuf[TM_C * APAD + n * APAD + kq * 4]);
        asm volatile("cp.async.cg.shared.global [%0], [%1], 16;" :: "r"(d0), "l"(&g_dtf[gi]) : "memory");
        asm volatile("cp.async.cg.shared.global [%0], [%1], 16;" :: "r"(d1), "l"(&g_dtf[NATOMS * ALEN + gi]) : "memory");
    }
}

// group-local barrier (GRPSZ co-resident CTAs of one batch)
__device__ __forceinline__ void gsync_grp(int grp) {
    __syncthreads();
    if (threadIdx.x == 0) {
        unsigned gen = atomicAdd(&g_gen8[grp], 0u);
        __threadfence();
        if (atomicInc(&g_cnt8[grp], GRPSZ - 1) == GRPSZ - 1) {
            atomicAdd(&g_gen8[grp], 1u);
        } else {
            while (atomicAdd(&g_gen8[grp], 0u) == gen) __nanosleep(32);
        }
        __threadfence();
    }
    __syncthreads();
}

// ---------------- setup ----------------
__global__ void k_norm(const float* __restrict__ d) {
    int n = blockIdx.x;
    int tid = threadIdx.x;
    __shared__ float red[256];
    float s = 0.f;
    for (int a = tid; a < ALEN; a += 256) { float v = d[n * ALEN + a]; s += v * v; }
    red[tid] = s; __syncthreads();
    for (int st = 128; st > 0; st >>= 1) {
        if (tid < st) red[tid] += red[tid + st];
        __syncthreads();
    }
    float inv = 1.0f / (sqrtf(red[0]) + EPS_N);
    for (int a = tid; a < ALEN; a += 256) {
        float v = d[n * ALEN + a] * inv;
        g_dn[n * ALEN + a] = v;
        uint32_t big = f2tf32(v);
        g_dtf[n * ALEN + a] = big;
        g_dtf[NATOMS * ALEN + n * ALEN + a] = f2tf32(v - __uint_as_float(big));
    }
}

__global__ void k_init_out(const float* __restrict__ x, float* __restrict__ out) {
    int i = blockIdx.x * blockDim.x + threadIdx.x;
    int n = BATCH * T_LEN;
    if (i < n) { out[i] = x[i]; out[n + i] = 0.f; }
    if (i < (N_ITER + 1) * BATCH) g_best[i] = 0ull;
}

// ---------------- full correlation (3xTF32, double-buffered, 2 CTAs/SM) ----------------
__global__ __launch_bounds__(256, 2) void k_conv_full(const float* __restrict__ x) {
    extern __shared__ __align__(16) uint32_t sm[];
    uint32_t* sA = sm;
    uint32_t* sS = sm + 4 * TM_C * APAD;

    const int b  = blockIdx.z;
    const int n0 = blockIdx.y * TM_C;
    const int t0 = blockIdx.x * TNP;
    const int tid = threadIdx.x;
    const int lane = tid & 31;
    const int wm = (tid >> 5) & 1;
    const int wn = tid >> 6;
    const int g = lane >> 2;
    const int tig = lane & 3;

    const float* sig = x + (size_t)b * T_LEN;

    stage_chunk_conv(sA, n0, 0, tid);
    CP_COMMIT();

    for (int i = tid; i < SWIN; i += 256) {
        int gi = t0 + i;
        float v = (gi < T_LEN) ? sig[gi] : 0.f;
        uint32_t big = f2tf32(v);
        sS[i] = big;
        sS[SSTR + i] = f2tf32(v - __uint_as_float(big));
    }

    float acc[2][NI][4];
    #pragma unroll
    for (int mi = 0; mi < 2; mi++)
        #pragma unroll
        for (int ni = 0; ni < NI; ni++)
            #pragma unroll
            for (int q = 0; q < 4; q++) acc[mi][ni][q] = 0.f;

    for (int i = 0; i < NCHUNK; i++) {
        if (i + 1 < NCHUNK) {
            stage_chunk_conv(sA + ((i + 1) & 1) * 2 * TM_C * APAD, n0, (i + 1) * KC, tid);
            CP_COMMIT();
            CP_WAIT1();
        } else {
            CP_WAIT0();
        }
        __syncthreads();
        const uint32_t* base = sA + (i & 1) * 2 * TM_C * APAD;
        const int a0 = i * KC;

        #pragma unroll
        for (int kk = 0; kk < KC / 8; kk++) {
            const int col = kk * 8 + tig;
            uint32_t Ab[2][4], As[2][4], Bb[NI][2], Bs[NI][2];
            #pragma unroll
            for (int mi = 0; mi < 2; mi++) {
                int rm = wm * 32 + mi * 16 + g;
                const uint32_t* p = &base[rm * APAD + col];
                Ab[mi][0] = p[0];
                Ab[mi][1] = p[8 * APAD];
                Ab[mi][2] = p[4];
                Ab[mi][3] = p[8 * APAD + 4];
                const uint32_t* q = p + TM_C * APAD;
                As[mi][0] = q[0];
                As[mi][1] = q[8 * APAD];
                As[mi][2] = q[4];
                As[mi][3] = q[8 * APAD + 4];
            }
            #pragma unroll
            for (int ni = 0; ni < NI; ni++) {
                int idx = wn * (TNP / 4) + ni * 8 + g + a0 + col;
                Bb[ni][0] = sS[idx];
                Bb[ni][1] = sS[idx + 4];
                Bs[ni][0] = sS[SSTR + idx];
                Bs[ni][1] = sS[SSTR + idx + 4];
            }
            #pragma unroll
            for (int mi = 0; mi < 2; mi++)
                #pragma unroll
                for (int ni = 0; ni < NI; ni++) {
                    mma8(acc[mi][ni], As[mi], Bb[ni]);
                    mma8(acc[mi][ni], Ab[mi], Bs[ni]);
                    mma8(acc[mi][ni], Ab[mi], Bb[ni]);
                }
        }
        __syncthreads();
    }

    #pragma unroll
    for (int mi = 0; mi < 2; mi++) {
        int n1 = n0 + wm * 32 + mi * 16 + g;
        float* row1 = g_fm + ((size_t)(b * NATOMS + n1)) * T_LEN;
        float* row2 = row1 + 8 * (size_t)T_LEN;
        #pragma unroll
        for (int ni = 0; ni < NI; ni++) {
            int tc = t0 + wn * (TNP / 4) + ni * 8 + tig * 2;
            *(float2*)(row1 + tc) = make_float2(acc[mi][ni][0], acc[mi][ni][1]);
            *(float2*)(row2 + tc) = make_float2(acc[mi][ni][2], acc[mi][ni][3]);
        }
    }
}

// ---------------- initial block-max: warp per 1024-block, MLP 8 ----------------
__global__ __launch_bounds__(256) void k_bmax_init() {
    int wid = threadIdx.x >> 5;
    int lane = threadIdx.x & 31;
    int unit = blockIdx.x * 8 + wid;          // 0 .. 65535
    int b  = unit >> 13;
    int n  = (unit >> 4) & (NATOMS - 1);
    int bl = unit & 15;
    const float* row = &g_fm[((size_t)(b * NATOMS + n)) * T_LEN + bl * BLKSZ];
    float bv = -3.402823466e38f;
    int bt = 0x7FFFFFFF;
    #pragma unroll
    for (int i = 0; i < 8; i++) {
        int base = (i * 32 + lane) * 4;
        float4 v = *(const float4*)&row[base];
        if (v.x > bv) { bv = v.x; bt = base; }
        if (v.y > bv) { bv = v.y; bt = base + 1; }
        if (v.z > bv) { bv = v.z; bt = base + 2; }
        if (v.w > bv) { bv = v.w; bt = base + 3; }
    }
    #pragma unroll
    for (int o = 16; o > 0; o >>= 1) {
        float ov = __shfl_down_sync(0xFFFFFFFFu, bv, o);
        int   ot = __shfl_down_sync(0xFFFFFFFFu, bt, o);
        if (ov > bv || (ov == bv && ot < bt)) { bv = ov; bt = ot; }
    }
    if (lane == 0) {
        int idx = (b * NATOMS + n) * NBLK + bl;
        g_bmax[idx] = bv;
        g_barg[idx] = bl * BLKSZ + bt;
    }
}

// ---------------- persistent loop: 16-atom slices, 2 CTAs/SM, 1 barrier/iter ----------------
__global__ __launch_bounds__(256, 2) void k_loop(float* __restrict__ out) {
    extern __shared__ __align__(16) uint32_t sm[];
    uint32_t* sA = sm;                    // [2 splits][16 n][KSTR]
    uint32_t* sS = sm + 2 * 16 * KSTR;    // [2 splits][SSL]
    __shared__ unsigned long long s_part[8];
    __shared__ unsigned long long s_best;

    const int grp = blockIdx.x >> 5;      // batch
    const int mem = blockIdx.x & 31;      // 16-atom slice
    const int n0 = mem * 16;
    const int tid = threadIdx.x;
    const int wid = tid >> 5;
    const int lane = tid & 31;
    const int g = lane >> 2;
    const int tig = lane & 3;

    // stage dictionary slice once (2 splits x 16 rows x 512 K)
    for (int e = tid; e < 2 * 16 * 128; e += 256) {
        int sp = e >> 11;
        int r  = (e >> 7) & 15;
        int kq = e & 127;
        size_t gi = (size_t)sp * NATOMS * ALEN + (size_t)(n0 + r) * ALEN + kq * 4;
        uint32_t dst = (uint32_t)__cvta_generic_to_shared(&sA[sp * 16 * KSTR + r * KSTR + kq * 4]);
        asm volatile("cp.async.cg.shared.global [%0], [%1], 16;" :: "r"(dst), "l"(&g_dtf[gi]) : "memory");
    }
    CP_COMMIT(); CP_WAIT0();
    __syncthreads();

    // initial A-scan -> g_best[0]
    {
        int base = (grp * NATOMS + n0) * NBLK;
        float v = g_bmax[base + tid];
        unsigned flat = (unsigned)((n0 + (tid >> 4)) * T_LEN + g_barg[base + tid]);
        unsigned long long best = pack_key(v, flat);
        #pragma unroll
        for (int o = 16; o > 0; o >>= 1) {
            unsigned long long ok = __shfl_down_sync(0xFFFFFFFFu, best, o);
            if (ok > best) best = ok;
        }
        if (lane == 0) s_part[wid] = best;
        __syncthreads();
        if (wid == 0) {
            unsigned long long b2 = (lane < 8) ? s_part[lane] : 0ull;
            #pragma unroll
            for (int o = 4; o > 0; o >>= 1) {
                unsigned long long ok = __shfl_down_sync(0xFFFFFFFFu, b2, o);
                if (ok > b2) b2 = ok;
            }
            if (lane == 0) atomicMax(&g_best[grp], b2);
        }
    }
    gsync_grp(grp);

    for (int it = 0; it < N_ITER; it++) {
        // ---- decode winner ----
        if (tid == 0) s_best = *((volatile unsigned long long*)&g_best[it * BATCH + grp]);
        __syncthreads();
        unsigned long long w = s_best;
        unsigned key = (unsigned)(w >> 32);
        unsigned uv = (key & 0x80000000u) ? (key & 0x7FFFFFFFu) : ~key;
        float v = __uint_as_float(uv);
        unsigned flat = 0xFFFFFFFFu - (unsigned)(w & 0xFFFFFFFFu);
        int n = (int)(flat >> 14);
        int t = (int)(flat & (T_LEN - 1));
        int L = min(t + ALEN, T_LEN - 1) - t;   // ref clips: position T-1 never written

        if (mem == 0) {
            float* res = out + (size_t)grp * T_LEN;
            float* rec = out + (size_t)(BATCH + grp) * T_LEN;
            for (int u = tid; u < L; u += 256) {
                float wv = v * g_dn[n * ALEN + u];
                res[t + u] -= wv;
                rec[t + u] += wv;
            }
        }
        if (it == N_ITER - 1) return;

        if (L > 0) {
            int toff = t - (ALEN - 1);
            // build tf32 splits of the delta signal directly from g_dn
            for (int i = tid; i < SIGL; i += 256) {
                int j = i - (ALEN - 1);
                float sv = (j >= 0 && j < L) ? v * g_dn[n * ALEN + j] : 0.f;
                uint32_t big = f2tf32(sv);
                sS[i] = big;
                sS[SSL + i] = f2tf32(sv - __uint_as_float(big));
            }
            __syncthreads();

            #pragma unroll
            for (int pass = 0; pass < 2; pass++) {
                int tw = pass * 512 + wid * 64;
                int klo = max(0, (ALEN - 1) - (tw + 63)) & ~7;
                int khi = min(ALEN, (ALEN - 1) + L - tw);
                khi = (khi + 7) & ~7;
                if (klo >= khi) continue;

                float acc[8][4];
                #pragma unroll
                for (int ni = 0; ni < 8; ni++)
                    #pragma unroll
                    for (int q = 0; q < 4; q++) acc[ni][q] = 0.f;

                for (int k0 = klo; k0 < khi; k0 += 8) {
                    int col = k0 + tig;
                    uint32_t Ab[4], As[4], Bb[8][2], Bs[8][2];
                    {
                        const uint32_t* p = &sA[g * KSTR + col];
                        Ab[0] = p[0];
                        Ab[1] = p[8 * KSTR];
                        Ab[2] = p[4];
                        Ab[3] = p[8 * KSTR + 4];
                        const uint32_t* q = p + 16 * KSTR;
                        As[0] = q[0];
                        As[1] = q[8 * KSTR];
                        As[2] = q[4];
                        As[3] = q[8 * KSTR + 4];
                    }
                    #pragma unroll
                    for (int ni = 0; ni < 8; ni++) {
                        int idx = tw + ni * 8 + g + col;
                        Bb[ni][0] = sS[idx];
                        Bb[ni][1] = sS[idx + 4];
                        Bs[ni][0] = sS[SSL + idx];
                        Bs[ni][1] = sS[SSL + idx + 4];
                    }
                    #pragma unroll
                    for (int ni = 0; ni < 8; ni++) {
                        mma8(acc[ni], As, Bb[ni]);
                        mma8(acc[ni], Ab, Bs[ni]);
                        mma8(acc[ni], Ab, Bb[ni]);
                    }
                }

                {
                    int n1 = n0 + g;
                    float* row1 = g_fm + ((size_t)(grp * NATOMS + n1)) * T_LEN;
                    float* row2 = row1 + 8 * (size_t)T_LEN;
                    #pragma unroll
                    for (int ni = 0; ni < 8; ni++) {
                        int tt = toff + tw + ni * 8 + tig * 2;
                        if (tt >= 0 && tt < T_LEN)         row1[tt]     -= acc[ni][0];
                        if (tt + 1 >= 0 && tt + 1 < T_LEN) row1[tt + 1] -= acc[ni][1];
                        if (tt >= 0 && tt < T_LEN)         row2[tt]     -= acc[ni][2];
                        if (tt + 1 >= 0 && tt + 1 < T_LEN) row2[tt + 1] -= acc[ni][3];
                    }
                }
            }
            __syncthreads();   // all delta stores visible CTA-wide before refresh reads

            // ---- refresh own rows' touched block maxima (16 rows x <=2 blocks) ----
            {
                int lo = max(0, t - (ALEN - 1));
                int hi = min(T_LEN - 1, t + (ALEN - 1));
                int bl0 = lo >> 10, bl1 = hi >> 10;
                for (int u = wid; u < 32; u += 8) {
                    int r = u >> 1;
                    int which = u & 1;
                    if (which && bl1 == bl0) continue;
                    int bl = which ? bl1 : bl0;
                    const float* row = &g_fm[((size_t)(grp * NATOMS + n0 + r)) * T_LEN + bl * BLKSZ];
                    float bv = -3.402823466e38f;
                    int bt = 0x7FFFFFFF;
                    #pragma unroll
                    for (int i = 0; i < 8; i++) {
                        int base = (i * 32 + lane) * 4;
                        float4 vv = *(const float4*)&row[base];
                        if (vv.x > bv) { bv = vv.x; bt = base; }
                        if (vv.y > bv) { bv = vv.y; bt = base + 1; }
                        if (vv.z > bv) { bv = vv.z; bt = base + 2; }
                        if (vv.w > bv) { bv = vv.w; bt = base + 3; }
                    }
                    #pragma unroll
                    for (int o = 16; o > 0; o >>= 1) {
                        float ov = __shfl_down_sync(0xFFFFFFFFu, bv, o);
                        int   ot = __shfl_down_sync(0xFFFFFFFFu, bt, o);
                        if (ov > bv || (ov == bv && ot < bt)) { bv = ov; bt = ot; }
                    }
                    if (lane == 0) {
                        int idx = (grp * NATOMS + n0 + r) * NBLK + bl;
                        g_bmax[idx] = bv;
                        g_barg[idx] = bl * BLKSZ + bt;
                    }
                }
            }
        }
        __syncthreads();   // refresh writes (own global rows) visible CTA-wide

        // ---- A-scan for it+1: own 256 keys -> one atomicMax ----
        {
            int base = (grp * NATOMS + n0) * NBLK;
            float bv = g_bmax[base + tid];
            unsigned fl = (unsigned)((n0 + (tid >> 4)) * T_LEN + g_barg[base + tid]);
            unsigned long long best = pack_key(bv, fl);
            #pragma unroll
            for (int o = 16; o > 0; o >>= 1) {
                unsigned long long ok = __shfl_down_sync(0xFFFFFFFFu, best, o);
                if (ok > best) best = ok;
            }
            if (lane == 0) s_part[wid] = best;
            __syncthreads();
            if (wid == 0) {
                unsigned long long b2 = (lane < 8) ? s_part[lane] : 0ull;
                #pragma unroll
                for (int o = 4; o > 0; o >>= 1) {
                    unsigned long long ok = __shfl_down_sync(0xFFFFFFFFu, b2, o);
                    if (ok > b2) b2 = ok;
                }
                if (lane == 0) atomicMax(&g_best[(it + 1) * BATCH + grp], b2);
            }
        }
        gsync_grp(grp);
    }
}

// ---------------- launch ----------------
extern "C" void kernel_launch(void* const* d_in, const int* in_sizes, int n_in,
                              void* d_out, int out_size) {
    const float* x = (const float*)d_in[0];
    const float* d = (const float*)d_in[1];
    float* out = (float*)d_out;

    cudaFuncSetAttribute(k_conv_full, cudaFuncAttributeMaxDynamicSharedMemorySize, CONV_SMEM);
    cudaFuncSetAttribute(k_loop,      cudaFuncAttributeMaxDynamicSharedMemorySize, LOOP_SMEM);

    k_norm<<<NATOMS, 256>>>(d);
    {
        int n = BATCH * T_LEN;
        k_init_out<<<(n + 255) / 256, 256>>>(x, out);
    }
    k_conv_full<<<dim3(T_LEN / TNP, NATOMS / TM_C, BATCH), 256, CONV_SMEM>>>(x);
    k_bmax_init<<<BATCH * NATOMS * NBLK / 8, 256>>>();
    k_loop<<<PCTAS, 256, LOOP_SMEM>>>(out);
}

// round 16
// speedup vs baseline: 1.4055x; 1.0124x over previous
#include <cuda_runtime.h>
#include <math.h>
#include <cstdint>

#define T_LEN   16384
#define NATOMS  512
#define ALEN    512
#define BATCH   8
#define NBLK    16
#define BLKSZ   1024
#define SIGL    1536
#define N_ITER  32
#define EPS_N   1e-8f

// full-conv tiling: TM_C=64 rows, TNP=128 cols, 2 CTAs/SM
#define TM_C 64
#define KC 64
#define NCHUNK (ALEN / KC)
#define APAD 68
#define TNP 128
#define NI  (TNP / 32)
#define SWIN (TNP + ALEN)
#define SSTR (SWIN + 8)
#define CONV_SMEM ((4 * TM_C * APAD + 2 * SSTR) * 4)     // 74816
// loop kernel: 16-atom slices, 2 CTAs/SM, smem key table
#define KSTR 516
#define SSL  1544
#define LOOP_SMEM (((2 * 16 * KSTR + 2 * SSL) * 4) + 2048)  // 80448
#define PCTAS 256
#define GRPSZ 32

// ---------------- device-global scratch ----------------
__device__ float g_dn[NATOMS * ALEN];
__device__ __align__(16) uint32_t g_dtf[2 * NATOMS * ALEN];
__device__ float g_fm[(size_t)BATCH * NATOMS * T_LEN];                  // 256 MB
__device__ unsigned long long g_part[(size_t)BATCH * NATOMS * 512];    // 16 MB partial keys (32-t grain)
__device__ unsigned long long g_bmaxp[BATCH * NATOMS * NBLK];          // per-block packed keys
__device__ unsigned long long g_best[(N_ITER + 1) * BATCH];
__device__ unsigned g_cnt8[BATCH] = {0};
__device__ unsigned g_gen8[BATCH] = {0};

// ---------------- helpers ----------------
__device__ __forceinline__ uint32_t f2tf32(float v) {
    uint32_t r;
    asm("cvt.rna.tf32.f32 %0, %1;" : "=r"(r) : "f"(v));
    return r;
}
__device__ __forceinline__ void mma8(float* c, const uint32_t* a, const uint32_t* b) {
    asm volatile(
        "mma.sync.aligned.m16n8k8.row.col.f32.tf32.tf32.f32 "
        "{%0,%1,%2,%3}, {%4,%5,%6,%7}, {%8,%9}, {%0,%1,%2,%3};"
        : "+f"(c[0]), "+f"(c[1]), "+f"(c[2]), "+f"(c[3])
        : "r"(a[0]), "r"(a[1]), "r"(a[2]), "r"(a[3]), "r"(b[0]), "r"(b[1]));
}
#define CP_COMMIT() asm volatile("cp.async.commit_group;" ::: "memory")
#define CP_WAIT0()  asm volatile("cp.async.wait_group 0;" ::: "memory")
#define CP_WAIT1()  asm volatile("cp.async.wait_group 1;" ::: "memory")

// monotonic float->uint key; low word = 0xFFFFFFFF - flat (first-on-tie via max)
__device__ __forceinline__ unsigned long long pack_key(float v, unsigned flat) {
    unsigned u = __float_as_uint(v);
    unsigned key = (u & 0x80000000u) ? ~u : (u | 0x80000000u);
    return ((unsigned long long)key << 32) | (0xFFFFFFFFu - flat);
}

// conv dict-chunk staging (TM_C rows)
__device__ __forceinline__ void stage_chunk_conv(uint32_t* sAbuf, int n0, int a0, int tid) {
    #pragma unroll
    for (int e = tid; e < TM_C * 16; e += 256) {
        int kq = e & 15, n = e >> 4;
        size_t gi = (size_t)(n0 + n) * ALEN + a0 + kq * 4;
        uint32_t d0 = (uint32_t)__cvta_generic_to_shared(&sAbuf[n * APAD + kq * 4]);
        uint32_t d1 = (uint32_t)__cvta_generic_to_shared(&sAbuf[TM_C * APAD + n * APAD + kq * 4]);
        asm volatile("cp.async.cg.shared.global [%0], [%1], 16;" :: "r"(d0), "l"(&g_dtf[gi]) : "memory");
        asm volatile("cp.async.cg.shared.global [%0], [%1], 16;" :: "r"(d1), "l"(&g_dtf[NATOMS * ALEN + gi]) : "memory");
    }
}

// group-local barrier (GRPSZ co-resident CTAs of one batch)
__device__ __forceinline__ void gsync_grp(int grp) {
    __syncthreads();
    if (threadIdx.x == 0) {
        unsigned gen = atomicAdd(&g_gen8[grp], 0u);
        __threadfence();
        if (atomicInc(&g_cnt8[grp], GRPSZ - 1) == GRPSZ - 1) {
            atomicAdd(&g_gen8[grp], 1u);
        } else {
            while (atomicAdd(&g_gen8[grp], 0u) == gen) __nanosleep(32);
        }
        __threadfence();
    }
    __syncthreads();
}

// ---------------- setup ----------------
__global__ void k_norm(const float* __restrict__ d) {
    int n = blockIdx.x;
    int tid = threadIdx.x;
    __shared__ float red[256];
    float s = 0.f;
    for (int a = tid; a < ALEN; a += 256) { float v = d[n * ALEN + a]; s += v * v; }
    red[tid] = s; __syncthreads();
    for (int st = 128; st > 0; st >>= 1) {
        if (tid < st) red[tid] += red[tid + st];
        __syncthreads();
    }
    float inv = 1.0f / (sqrtf(red[0]) + EPS_N);
    for (int a = tid; a < ALEN; a += 256) {
        float v = d[n * ALEN + a] * inv;
        g_dn[n * ALEN + a] = v;
        uint32_t big = f2tf32(v);
        g_dtf[n * ALEN + a] = big;
        g_dtf[NATOMS * ALEN + n * ALEN + a] = f2tf32(v - __uint_as_float(big));
    }
}

__global__ void k_init_out(const float* __restrict__ x, float* __restrict__ out) {
    int i = blockIdx.x * blockDim.x + threadIdx.x;
    int n = BATCH * T_LEN;
    if (i < n) { out[i] = x[i]; out[n + i] = 0.f; }
    if (i < (N_ITER + 1) * BATCH) g_best[i] = 0ull;
}

// ---------------- full correlation + fused partial block-max (no atomics) ----------------
__global__ __launch_bounds__(256, 2) void k_conv_full(const float* __restrict__ x) {
    extern __shared__ __align__(16) uint32_t sm[];
    uint32_t* sA = sm;
    uint32_t* sS = sm + 4 * TM_C * APAD;

    const int b  = blockIdx.z;
    const int n0 = blockIdx.y * TM_C;
    const int t0 = blockIdx.x * TNP;
    const int tid = threadIdx.x;
    const int lane = tid & 31;
    const int wm = (tid >> 5) & 1;
    const int wn = tid >> 6;
    const int g = lane >> 2;
    const int tig = lane & 3;

    const float* sig = x + (size_t)b * T_LEN;

    stage_chunk_conv(sA, n0, 0, tid);
    CP_COMMIT();

    for (int i = tid; i < SWIN; i += 256) {
        int gi = t0 + i;
        float v = (gi < T_LEN) ? sig[gi] : 0.f;
        uint32_t big = f2tf32(v);
        sS[i] = big;
        sS[SSTR + i] = f2tf32(v - __uint_as_float(big));
    }

    float acc[2][NI][4];
    #pragma unroll
    for (int mi = 0; mi < 2; mi++)
        #pragma unroll
        for (int ni = 0; ni < NI; ni++)
            #pragma unroll
            for (int q = 0; q < 4; q++) acc[mi][ni][q] = 0.f;

    for (int i = 0; i < NCHUNK; i++) {
        if (i + 1 < NCHUNK) {
            stage_chunk_conv(sA + ((i + 1) & 1) * 2 * TM_C * APAD, n0, (i + 1) * KC, tid);
            CP_COMMIT();
            CP_WAIT1();
        } else {
            CP_WAIT0();
        }
        __syncthreads();
        const uint32_t* base = sA + (i & 1) * 2 * TM_C * APAD;
        const int a0 = i * KC;

        #pragma unroll
        for (int kk = 0; kk < KC / 8; kk++) {
            const int col = kk * 8 + tig;
            uint32_t Ab[2][4], As[2][4], Bb[NI][2], Bs[NI][2];
            #pragma unroll
            for (int mi = 0; mi < 2; mi++) {
                int rm = wm * 32 + mi * 16 + g;
                const uint32_t* p = &base[rm * APAD + col];
                Ab[mi][0] = p[0];
                Ab[mi][1] = p[8 * APAD];
                Ab[mi][2] = p[4];
                Ab[mi][3] = p[8 * APAD + 4];
                const uint32_t* q = p + TM_C * APAD;
                As[mi][0] = q[0];
                As[mi][1] = q[8 * APAD];
                As[mi][2] = q[4];
                As[mi][3] = q[8 * APAD + 4];
            }
            #pragma unroll
            for (int ni = 0; ni < NI; ni++) {
                int idx = wn * (TNP / 4) + ni * 8 + g + a0 + col;
                Bb[ni][0] = sS[idx];
                Bb[ni][1] = sS[idx + 4];
                Bs[ni][0] = sS[SSTR + idx];
                Bs[ni][1] = sS[SSTR + idx + 4];
            }
            #pragma unroll
            for (int mi = 0; mi < 2; mi++)
                #pragma unroll
                for (int ni = 0; ni < NI; ni++) {
                    mma8(acc[mi][ni], As[mi], Bb[ni]);
                    mma8(acc[mi][ni], Ab[mi], Bs[ni]);
                    mma8(acc[mi][ni], Ab[mi], Bb[ni]);
                }
        }
        __syncthreads();
    }

    // epilogue: store fm + per-(row, 32-t subtile) partial max key (no atomics)
    const int sub = (t0 + wn * 32) >> 5;     // global 32-t subtile index
    #pragma unroll
    for (int mi = 0; mi < 2; mi++) {
        int n1 = n0 + wm * 32 + mi * 16 + g;
        int n2 = n1 + 8;
        float* row1 = g_fm + ((size_t)(b * NATOMS + n1)) * T_LEN;
        float* row2 = row1 + 8 * (size_t)T_LEN;
        float bv1 = -3.402823466e38f, bv2 = -3.402823466e38f;
        int bt1 = 0, bt2 = 0;
        #pragma unroll
        for (int ni = 0; ni < NI; ni++) {
            int tc = t0 + wn * (TNP / 4) + ni * 8 + tig * 2;
            *(float2*)(row1 + tc) = make_float2(acc[mi][ni][0], acc[mi][ni][1]);
            *(float2*)(row2 + tc) = make_float2(acc[mi][ni][2], acc[mi][ni][3]);
            if (acc[mi][ni][0] > bv1) { bv1 = acc[mi][ni][0]; bt1 = tc; }
            if (acc[mi][ni][1] > bv1) { bv1 = acc[mi][ni][1]; bt1 = tc + 1; }
            if (acc[mi][ni][2] > bv2) { bv2 = acc[mi][ni][2]; bt2 = tc; }
            if (acc[mi][ni][3] > bv2) { bv2 = acc[mi][ni][3]; bt2 = tc + 1; }
        }
        #pragma unroll
        for (int o = 1; o < 4; o <<= 1) {
            float ov1 = __shfl_down_sync(0xFFFFFFFFu, bv1, o, 4);
            int   ot1 = __shfl_down_sync(0xFFFFFFFFu, bt1, o, 4);
            float ov2 = __shfl_down_sync(0xFFFFFFFFu, bv2, o, 4);
            int   ot2 = __shfl_down_sync(0xFFFFFFFFu, bt2, o, 4);
            if (ov1 > bv1 || (ov1 == bv1 && ot1 < bt1)) { bv1 = ov1; bt1 = ot1; }
            if (ov2 > bv2 || (ov2 == bv2 && ot2 < bt2)) { bv2 = ov2; bt2 = ot2; }
        }
        if (tig == 0) {
            g_part[((size_t)(b * NATOMS + n1)) * 512 + sub] =
                pack_key(bv1, (unsigned)(n1 * T_LEN + bt1));
            g_part[((size_t)(b * NATOMS + n2)) * 512 + sub] =
                pack_key(bv2, (unsigned)(n2 * T_LEN + bt2));
        }
    }
}

// ---------------- block-max from partials: warp per (b,n,bl), 256B each ----------------
__global__ __launch_bounds__(256) void k_bmax_init() {
    int wid = threadIdx.x >> 5;
    int lane = threadIdx.x & 31;
    int unit = blockIdx.x * 8 + wid;          // 0 .. 65535 = (b*NATOMS+n)*NBLK+bl
    unsigned long long best = g_part[(size_t)unit * 32 + lane];
    #pragma unroll
    for (int o = 16; o > 0; o >>= 1) {
        unsigned long long ok = __shfl_down_sync(0xFFFFFFFFu, best, o);
        if (ok > best) best = ok;
    }
    if (lane == 0) g_bmaxp[unit] = best;
}

// ---------------- persistent loop: smem key table, 1 barrier/iter, 2 CTAs/SM ----------------
__global__ __launch_bounds__(256, 2) void k_loop(float* __restrict__ out) {
    extern __shared__ __align__(16) uint32_t sm[];
    uint32_t* sA = sm;                    // [2 splits][16 n][KSTR]
    uint32_t* sS = sm + 2 * 16 * KSTR;    // [2 splits][SSL]
    unsigned long long* sBK = (unsigned long long*)(sm + 2 * 16 * KSTR + 2 * SSL);  // [256] keys
    __shared__ unsigned long long s_part[8];
    __shared__ unsigned long long s_best;

    const int grp = blockIdx.x >> 5;      // batch
    const int mem = blockIdx.x & 31;      // 16-atom slice
    const int n0 = mem * 16;
    const int tid = threadIdx.x;
    const int wid = tid >> 5;
    const int lane = tid & 31;
    const int g = lane >> 2;
    const int tig = lane & 3;

    // stage dictionary slice once (2 splits x 16 rows x 512 K)
    for (int e = tid; e < 2 * 16 * 128; e += 256) {
        int sp = e >> 11;
        int r  = (e >> 7) & 15;
        int kq = e & 127;
        size_t gi = (size_t)sp * NATOMS * ALEN + (size_t)(n0 + r) * ALEN + kq * 4;
        uint32_t dst = (uint32_t)__cvta_generic_to_shared(&sA[sp * 16 * KSTR + r * KSTR + kq * 4]);
        asm volatile("cp.async.cg.shared.global [%0], [%1], 16;" :: "r"(dst), "l"(&g_dtf[gi]) : "memory");
    }
    CP_COMMIT();

    // load own block-max keys into smem (16 atoms x 16 blocks)
    sBK[tid] = g_bmaxp[(grp * NATOMS + n0) * NBLK + tid];
    CP_WAIT0();
    __syncthreads();

    // initial A-scan -> g_best[0]
    {
        unsigned long long best = sBK[tid];
        #pragma unroll
        for (int o = 16; o > 0; o >>= 1) {
            unsigned long long ok = __shfl_down_sync(0xFFFFFFFFu, best, o);
            if (ok > best) best = ok;
        }
        if (lane == 0) s_part[wid] = best;
        __syncthreads();
        if (wid == 0) {
            unsigned long long b2 = (lane < 8) ? s_part[lane] : 0ull;
            #pragma unroll
            for (int o = 4; o > 0; o >>= 1) {
                unsigned long long ok = __shfl_down_sync(0xFFFFFFFFu, b2, o);
                if (ok > b2) b2 = ok;
            }
            if (lane == 0) atomicMax(&g_best[grp], b2);
        }
    }
    gsync_grp(grp);

    for (int it = 0; it < N_ITER; it++) {
        // ---- decode winner ----
        if (tid == 0) s_best = *((volatile unsigned long long*)&g_best[it * BATCH + grp]);
        __syncthreads();
        unsigned long long w = s_best;
        unsigned key = (unsigned)(w >> 32);
        unsigned uv = (key & 0x80000000u) ? (key & 0x7FFFFFFFu) : ~key;
        float v = __uint_as_float(uv);
        unsigned flat = 0xFFFFFFFFu - (unsigned)(w & 0xFFFFFFFFu);
        int n = (int)(flat >> 14);
        int t = (int)(flat & (T_LEN - 1));
        int L = min(t + ALEN, T_LEN - 1) - t;   // ref clips: position T-1 never written

        if (mem == 0) {
            float* res = out + (size_t)grp * T_LEN;
            float* rec = out + (size_t)(BATCH + grp) * T_LEN;
            for (int u = tid; u < L; u += 256) {
                float wv = v * g_dn[n * ALEN + u];
                res[t + u] -= wv;
                rec[t + u] += wv;
            }
        }
        if (it == N_ITER - 1) return;

        if (L > 0) {
            int toff = t - (ALEN - 1);
            // build tf32 splits of the delta signal directly from g_dn
            for (int i = tid; i < SIGL; i += 256) {
                int j = i - (ALEN - 1);
                float sv = (j >= 0 && j < L) ? v * g_dn[n * ALEN + j] : 0.f;
                uint32_t big = f2tf32(sv);
                sS[i] = big;
                sS[SSL + i] = f2tf32(sv - __uint_as_float(big));
            }
            __syncthreads();

            #pragma unroll
            for (int pass = 0; pass < 2; pass++) {
                int tw = pass * 512 + wid * 64;
                int klo = max(0, (ALEN - 1) - (tw + 63)) & ~7;
                int khi = min(ALEN, (ALEN - 1) + L - tw);
                khi = (khi + 7) & ~7;
                if (klo >= khi) continue;

                float acc[8][4];
                #pragma unroll
                for (int ni = 0; ni < 8; ni++)
                    #pragma unroll
                    for (int q = 0; q < 4; q++) acc[ni][q] = 0.f;

                for (int k0 = klo; k0 < khi; k0 += 8) {
                    int col = k0 + tig;
                    uint32_t Ab[4], As[4], Bb[8][2], Bs[8][2];
                    {
                        const uint32_t* p = &sA[g * KSTR + col];
                        Ab[0] = p[0];
                        Ab[1] = p[8 * KSTR];
                        Ab[2] = p[4];
                        Ab[3] = p[8 * KSTR + 4];
                        const uint32_t* q = p + 16 * KSTR;
                        As[0] = q[0];
                        As[1] = q[8 * KSTR];
                        As[2] = q[4];
                        As[3] = q[8 * KSTR + 4];
                    }
                    #pragma unroll
                    for (int ni = 0; ni < 8; ni++) {
                        int idx = tw + ni * 8 + g + col;
                        Bb[ni][0] = sS[idx];
                        Bb[ni][1] = sS[idx + 4];
                        Bs[ni][0] = sS[SSL + idx];
                        Bs[ni][1] = sS[SSL + idx + 4];
                    }
                    #pragma unroll
                    for (int ni = 0; ni < 8; ni++) {
                        mma8(acc[ni], As, Bb[ni]);
                        mma8(acc[ni], Ab, Bs[ni]);
                        mma8(acc[ni], Ab, Bb[ni]);
                    }
                }

                {
                    int n1 = n0 + g;
                    float* row1 = g_fm + ((size_t)(grp * NATOMS + n1)) * T_LEN;
                    float* row2 = row1 + 8 * (size_t)T_LEN;
                    #pragma unroll
                    for (int ni = 0; ni < 8; ni++) {
                        int tt = toff + tw + ni * 8 + tig * 2;
                        if (tt >= 0 && tt < T_LEN)         row1[tt]     -= acc[ni][0];
                        if (tt + 1 >= 0 && tt + 1 < T_LEN) row1[tt + 1] -= acc[ni][1];
                        if (tt >= 0 && tt < T_LEN)         row2[tt]     -= acc[ni][2];
                        if (tt + 1 >= 0 && tt + 1 < T_LEN) row2[tt + 1] -= acc[ni][3];
                    }
                }
            }
            __syncthreads();   // all delta stores visible CTA-wide before refresh reads

            // ---- refresh own rows' touched block maxima -> smem keys ----
            {
                int lo = max(0, t - (ALEN - 1));
                int hi = min(T_LEN - 1, t + (ALEN - 1));
                int bl0 = lo >> 10, bl1 = hi >> 10;
                for (int u = wid; u < 32; u += 8) {
                    int r = u >> 1;
                    int which = u & 1;
                    if (which && bl1 == bl0) continue;
                    int bl = which ? bl1 : bl0;
                    const float* row = &g_fm[((size_t)(grp * NATOMS + n0 + r)) * T_LEN + bl * BLKSZ];
                    float bv = -3.402823466e38f;
                    int bt = 0x7FFFFFFF;
                    #pragma unroll
                    for (int i = 0; i < 8; i++) {
                        int base = (i * 32 + lane) * 4;
                        float4 vv = *(const float4*)&row[base];
                        if (vv.x > bv) { bv = vv.x; bt = base; }
                        if (vv.y > bv) { bv = vv.y; bt = base + 1; }
                        if (vv.z > bv) { bv = vv.z; bt = base + 2; }
                        if (vv.w > bv) { bv = vv.w; bt = base + 3; }
                    }
                    #pragma unroll
                    for (int o = 16; o > 0; o >>= 1) {
                        float ov = __shfl_down_sync(0xFFFFFFFFu, bv, o);
                        int   ot = __shfl_down_sync(0xFFFFFFFFu, bt, o);
                        if (ov > bv || (ov == bv && ot < bt)) { bv = ov; bt = ot; }
                    }
                    if (lane == 0)
                        sBK[r * NBLK + bl] =
                            pack_key(bv, (unsigned)((n0 + r) * T_LEN + bl * BLKSZ + bt));
                }
            }
        }
        __syncthreads();   // sBK updates visible CTA-wide

        // ---- A-scan for it+1 from smem keys ----
        {
            unsigned long long best = sBK[tid];
            #pragma unroll
            for (int o = 16; o > 0; o >>= 1) {
                unsigned long long ok = __shfl_down_sync(0xFFFFFFFFu, best, o);
                if (ok > best) best = ok;
            }
            if (lane == 0) s_part[wid] = best;
            __syncthreads();
            if (wid == 0) {
                unsigned long long b2 = (lane < 8) ? s_part[lane] : 0ull;
                #pragma unroll
                for (int o = 4; o > 0; o >>= 1) {
                    unsigned long long ok = __shfl_down_sync(0xFFFFFFFFu, b2, o);
                    if (ok > b2) b2 = ok;
                }
                if (lane == 0) atomicMax(&g_best[(it + 1) * BATCH + grp], b2);
            }
        }
        gsync_grp(grp);
    }
}

// ---------------- launch ----------------
extern "C" void kernel_launch(void* const* d_in, const int* in_sizes, int n_in,
                              void* d_out, int out_size) {
    const float* x = (const float*)d_in[0];
    const float* d = (const float*)d_in[1];
    float* out = (float*)d_out;

    cudaFuncSetAttribute(k_conv_full, cudaFuncAttributeMaxDynamicSharedMemorySize, CONV_SMEM);
    cudaFuncSetAttribute(k_loop,      cudaFuncAttributeMaxDynamicSharedMemorySize, LOOP_SMEM);

    k_norm<<<NATOMS, 256>>>(d);
    {
        int n = BATCH * T_LEN;
        k_init_out<<<(n + 255) / 256, 256>>>(x, out);
    }
    k_conv_full<<<dim3(T_LEN / TNP, NATOMS / TM_C, BATCH), 256, CONV_SMEM>>>(x);
    k_bmax_init<<<BATCH * NATOMS * NBLK / 8, 256>>>();
    k_loop<<<PCTAS, 256, LOOP_SMEM>>>(out);
}

// round 17
// speedup vs baseline: 1.5438x; 1.0984x over previous
#include <cuda_runtime.h>
#include <math.h>
#include <cstdint>

#define T_LEN   16384
#define NATOMS  512
#define ALEN    512
#define BATCH   8
#define NBLK    16
#define BLKSZ   1024
#define SIGL    1536
#define N_ITER  32
#define EPS_N   1e-8f

// full-conv tiling: TM_C=64 rows, TNP=128 cols, 2 CTAs/SM
#define TM_C 64
#define KC 64
#define NCHUNK (ALEN / KC)
#define APAD 68
#define TNP 128
#define NI  (TNP / 32)
#define SWIN (TNP + ALEN)
#define SSTR (SWIN + 8)
#define CONV_SMEM ((4 * TM_C * APAD + 2 * SSTR) * 4)     // 74816
// loop kernel: 16-atom slices, 2 CTAs/SM, smem key table
#define KSTR 516
#define SSL  1544
#define LOOP_SMEM (((2 * 16 * KSTR + 2 * SSL) * 4) + 2048)  // 80448
#define PCTAS 256
#define GRPSZ 32

// ---------------- device-global scratch ----------------
__device__ float g_dn[NATOMS * ALEN];
__device__ __align__(16) uint32_t g_dtf[2 * NATOMS * ALEN];
__device__ float g_fm[(size_t)BATCH * NATOMS * T_LEN];                  // 256 MB
__device__ unsigned long long g_part[(size_t)BATCH * NATOMS * 512];    // 16 MB partial keys
__device__ unsigned long long g_bmaxp[BATCH * NATOMS * NBLK];
__device__ unsigned long long g_best[(N_ITER + 1) * BATCH];
__device__ unsigned g_cnt8[BATCH] = {0};
__device__ unsigned g_gen8[BATCH] = {0};

// ---------------- helpers ----------------
__device__ __forceinline__ uint32_t f2tf32(float v) {
    uint32_t r;
    asm("cvt.rna.tf32.f32 %0, %1;" : "=r"(r) : "f"(v));
    return r;
}
__device__ __forceinline__ void mma8(float* c, const uint32_t* a, const uint32_t* b) {
    asm volatile(
        "mma.sync.aligned.m16n8k8.row.col.f32.tf32.tf32.f32 "
        "{%0,%1,%2,%3}, {%4,%5,%6,%7}, {%8,%9}, {%0,%1,%2,%3};"
        : "+f"(c[0]), "+f"(c[1]), "+f"(c[2]), "+f"(c[3])
        : "r"(a[0]), "r"(a[1]), "r"(a[2]), "r"(a[3]), "r"(b[0]), "r"(b[1]));
}
#define CP_COMMIT() asm volatile("cp.async.commit_group;" ::: "memory")
#define CP_WAIT0()  asm volatile("cp.async.wait_group 0;" ::: "memory")
#define CP_WAIT1()  asm volatile("cp.async.wait_group 1;" ::: "memory")

// monotonic float->uint key; low word = 0xFFFFFFFF - flat (first-on-tie via max)
__device__ __forceinline__ unsigned long long pack_key(float v, unsigned flat) {
    unsigned u = __float_as_uint(v);
    unsigned key = (u & 0x80000000u) ? ~u : (u | 0x80000000u);
    return ((unsigned long long)key << 32) | (0xFFFFFFFFu - flat);
}

// conv dict-chunk staging (TM_C rows)
__device__ __forceinline__ void stage_chunk_conv(uint32_t* sAbuf, int n0, int a0, int tid) {
    #pragma unroll
    for (int e = tid; e < TM_C * 16; e += 256) {
        int kq = e & 15, n = e >> 4;
        size_t gi = (size_t)(n0 + n) * ALEN + a0 + kq * 4;
        uint32_t d0 = (uint32_t)__cvta_generic_to_shared(&sAbuf[n * APAD + kq * 4]);
        uint32_t d1 = (uint32_t)__cvta_generic_to_shared(&sAbuf[TM_C * APAD + n * APAD + kq * 4]);
        asm volatile("cp.async.cg.shared.global [%0], [%1], 16;" :: "r"(d0), "l"(&g_dtf[gi]) : "memory");
        asm volatile("cp.async.cg.shared.global [%0], [%1], 16;" :: "r"(d1), "l"(&g_dtf[NATOMS * ALEN + gi]) : "memory");
    }
}

// group-local barrier (GRPSZ co-resident CTAs of one batch)
__device__ __forceinline__ void gsync_grp(int grp) {
    __syncthreads();
    if (threadIdx.x == 0) {
        unsigned gen = atomicAdd(&g_gen8[grp], 0u);
        __threadfence();
        if (atomicInc(&g_cnt8[grp], GRPSZ - 1) == GRPSZ - 1) {
            atomicAdd(&g_gen8[grp], 1u);
        } else {
            while (atomicAdd(&g_gen8[grp], 0u) == gen) __nanosleep(32);
        }
        __threadfence();
    }
    __syncthreads();
}

// ---------------- setup ----------------
__global__ void k_norm(const float* __restrict__ d) {
    int n = blockIdx.x;
    int tid = threadIdx.x;
    __shared__ float red[256];
    float s = 0.f;
    for (int a = tid; a < ALEN; a += 256) { float v = d[n * ALEN + a]; s += v * v; }
    red[tid] = s; __syncthreads();
    for (int st = 128; st > 0; st >>= 1) {
        if (tid < st) red[tid] += red[tid + st];
        __syncthreads();
    }
    float inv = 1.0f / (sqrtf(red[0]) + EPS_N);
    for (int a = tid; a < ALEN; a += 256) {
        float v = d[n * ALEN + a] * inv;
        g_dn[n * ALEN + a] = v;
        uint32_t big = f2tf32(v);
        g_dtf[n * ALEN + a] = big;
        g_dtf[NATOMS * ALEN + n * ALEN + a] = f2tf32(v - __uint_as_float(big));
    }
}

__global__ void k_init_out(const float* __restrict__ x, float* __restrict__ out) {
    int i = blockIdx.x * blockDim.x + threadIdx.x;
    int n = BATCH * T_LEN;
    if (i < n) { out[i] = x[i]; out[n + i] = 0.f; }
    if (i < (N_ITER + 1) * BATCH) g_best[i] = 0ull;
}

// ---------------- full correlation + fused partial block-max ----------------
__global__ __launch_bounds__(256, 2) void k_conv_full(const float* __restrict__ x) {
    extern __shared__ __align__(16) uint32_t sm[];
    uint32_t* sA = sm;
    uint32_t* sS = sm + 4 * TM_C * APAD;

    const int b  = blockIdx.z;
    const int n0 = blockIdx.y * TM_C;
    const int t0 = blockIdx.x * TNP;
    const int tid = threadIdx.x;
    const int lane = tid & 31;
    const int wm = (tid >> 5) & 1;
    const int wn = tid >> 6;
    const int g = lane >> 2;
    const int tig = lane & 3;

    const float* sig = x + (size_t)b * T_LEN;

    stage_chunk_conv(sA, n0, 0, tid);
    CP_COMMIT();

    for (int i = tid; i < SWIN; i += 256) {
        int gi = t0 + i;
        float v = (gi < T_LEN) ? sig[gi] : 0.f;
        uint32_t big = f2tf32(v);
        sS[i] = big;
        sS[SSTR + i] = f2tf32(v - __uint_as_float(big));
    }

    float acc[2][NI][4];
    #pragma unroll
    for (int mi = 0; mi < 2; mi++)
        #pragma unroll
        for (int ni = 0; ni < NI; ni++)
            #pragma unroll
            for (int q = 0; q < 4; q++) acc[mi][ni][q] = 0.f;

    for (int i = 0; i < NCHUNK; i++) {
        if (i + 1 < NCHUNK) {
            stage_chunk_conv(sA + ((i + 1) & 1) * 2 * TM_C * APAD, n0, (i + 1) * KC, tid);
            CP_COMMIT();
            CP_WAIT1();
        } else {
            CP_WAIT0();
        }
        __syncthreads();
        const uint32_t* base = sA + (i & 1) * 2 * TM_C * APAD;
        const int a0 = i * KC;

        #pragma unroll
        for (int kk = 0; kk < KC / 8; kk++) {
            const int col = kk * 8 + tig;
            uint32_t Ab[2][4], As[2][4], Bb[NI][2], Bs[NI][2];
            #pragma unroll
            for (int mi = 0; mi < 2; mi++) {
                int rm = wm * 32 + mi * 16 + g;
                const uint32_t* p = &base[rm * APAD + col];
                Ab[mi][0] = p[0];
                Ab[mi][1] = p[8 * APAD];
                Ab[mi][2] = p[4];
                Ab[mi][3] = p[8 * APAD + 4];
                const uint32_t* q = p + TM_C * APAD;
                As[mi][0] = q[0];
                As[mi][1] = q[8 * APAD];
                As[mi][2] = q[4];
                As[mi][3] = q[8 * APAD + 4];
            }
            #pragma unroll
            for (int ni = 0; ni < NI; ni++) {
                int idx = wn * (TNP / 4) + ni * 8 + g + a0 + col;
                Bb[ni][0] = sS[idx];
                Bb[ni][1] = sS[idx + 4];
                Bs[ni][0] = sS[SSTR + idx];
                Bs[ni][1] = sS[SSTR + idx + 4];
            }
            #pragma unroll
            for (int mi = 0; mi < 2; mi++)
                #pragma unroll
                for (int ni = 0; ni < NI; ni++) {
                    mma8(acc[mi][ni], As[mi], Bb[ni]);
                    mma8(acc[mi][ni], Ab[mi], Bs[ni]);
                    mma8(acc[mi][ni], Ab[mi], Bb[ni]);
                }
        }
        __syncthreads();
    }

    const int sub = (t0 + wn * 32) >> 5;
    #pragma unroll
    for (int mi = 0; mi < 2; mi++) {
        int n1 = n0 + wm * 32 + mi * 16 + g;
        int n2 = n1 + 8;
        float* row1 = g_fm + ((size_t)(b * NATOMS + n1)) * T_LEN;
        float* row2 = row1 + 8 * (size_t)T_LEN;
        float bv1 = -3.402823466e38f, bv2 = -3.402823466e38f;
        int bt1 = 0, bt2 = 0;
        #pragma unroll
        for (int ni = 0; ni < NI; ni++) {
            int tc = t0 + wn * (TNP / 4) + ni * 8 + tig * 2;
            *(float2*)(row1 + tc) = make_float2(acc[mi][ni][0], acc[mi][ni][1]);
            *(float2*)(row2 + tc) = make_float2(acc[mi][ni][2], acc[mi][ni][3]);
            if (acc[mi][ni][0] > bv1) { bv1 = acc[mi][ni][0]; bt1 = tc; }
            if (acc[mi][ni][1] > bv1) { bv1 = acc[mi][ni][1]; bt1 = tc + 1; }
            if (acc[mi][ni][2] > bv2) { bv2 = acc[mi][ni][2]; bt2 = tc; }
            if (acc[mi][ni][3] > bv2) { bv2 = acc[mi][ni][3]; bt2 = tc + 1; }
        }
        #pragma unroll
        for (int o = 1; o < 4; o <<= 1) {
            float ov1 = __shfl_down_sync(0xFFFFFFFFu, bv1, o, 4);
            int   ot1 = __shfl_down_sync(0xFFFFFFFFu, bt1, o, 4);
            float ov2 = __shfl_down_sync(0xFFFFFFFFu, bv2, o, 4);
            int   ot2 = __shfl_down_sync(0xFFFFFFFFu, bt2, o, 4);
            if (ov1 > bv1 || (ov1 == bv1 && ot1 < bt1)) { bv1 = ov1; bt1 = ot1; }
            if (ov2 > bv2 || (ov2 == bv2 && ot2 < bt2)) { bv2 = ov2; bt2 = ot2; }
        }
        if (tig == 0) {
            g_part[((size_t)(b * NATOMS + n1)) * 512 + sub] =
                pack_key(bv1, (unsigned)(n1 * T_LEN + bt1));
            g_part[((size_t)(b * NATOMS + n2)) * 512 + sub] =
                pack_key(bv2, (unsigned)(n2 * T_LEN + bt2));
        }
    }
}

// ---------------- block-max from partials ----------------
__global__ __launch_bounds__(256) void k_bmax_init() {
    int wid = threadIdx.x >> 5;
    int lane = threadIdx.x & 31;
    int unit = blockIdx.x * 8 + wid;
    unsigned long long best = g_part[(size_t)unit * 32 + lane];
    #pragma unroll
    for (int o = 16; o > 0; o >>= 1) {
        unsigned long long ok = __shfl_down_sync(0xFFFFFFFFu, best, o);
        if (ok > best) best = ok;
    }
    if (lane == 0) g_bmaxp[unit] = best;
}

// ---------------- persistent loop ----------------
__global__ __launch_bounds__(256, 2) void k_loop(float* __restrict__ out) {
    extern __shared__ __align__(16) uint32_t sm[];
    uint32_t* sA = sm;                    // [2 splits][16 n][KSTR]
    uint32_t* sS = sm + 2 * 16 * KSTR;    // [2 splits][SSL]
    unsigned long long* sBK = (unsigned long long*)(sm + 2 * 16 * KSTR + 2 * SSL);  // [256]
    __shared__ unsigned long long s_part[8];

    const int grp = blockIdx.x >> 5;
    const int mem = blockIdx.x & 31;
    const int n0 = mem * 16;
    const int tid = threadIdx.x;
    const int wid = tid >> 5;
    const int lane = tid & 31;
    const int g = lane >> 2;
    const int tig = lane & 3;

    // stage dictionary slice once
    for (int e = tid; e < 2 * 16 * 128; e += 256) {
        int sp = e >> 11;
        int r  = (e >> 7) & 15;
        int kq = e & 127;
        size_t gi = (size_t)sp * NATOMS * ALEN + (size_t)(n0 + r) * ALEN + kq * 4;
        uint32_t dst = (uint32_t)__cvta_generic_to_shared(&sA[sp * 16 * KSTR + r * KSTR + kq * 4]);
        asm volatile("cp.async.cg.shared.global [%0], [%1], 16;" :: "r"(dst), "l"(&g_dtf[gi]) : "memory");
    }
    CP_COMMIT();

    sBK[tid] = g_bmaxp[(grp * NATOMS + n0) * NBLK + tid];
    CP_WAIT0();
    __syncthreads();

    // initial A-scan -> g_best[0]
    {
        unsigned long long best = sBK[tid];
        #pragma unroll
        for (int o = 16; o > 0; o >>= 1) {
            unsigned long long ok = __shfl_down_sync(0xFFFFFFFFu, best, o);
            if (ok > best) best = ok;
        }
        if (lane == 0) s_part[wid] = best;
        __syncthreads();
        if (wid == 0) {
            unsigned long long b2 = (lane < 8) ? s_part[lane] : 0ull;
            #pragma unroll
            for (int o = 4; o > 0; o >>= 1) {
                unsigned long long ok = __shfl_down_sync(0xFFFFFFFFu, b2, o);
                if (ok > b2) b2 = ok;
            }
            if (lane == 0) atomicMax(&g_best[grp], b2);
        }
    }
    gsync_grp(grp);

    for (int it = 0; it < N_ITER; it++) {
        // ---- decode winner: broadcast LDG by all threads ----
        unsigned long long w = *((volatile unsigned long long*)&g_best[it * BATCH + grp]);
        unsigned key = (unsigned)(w >> 32);
        unsigned uv = (key & 0x80000000u) ? (key & 0x7FFFFFFFu) : ~key;
        float v = __uint_as_float(uv);
        unsigned flat = 0xFFFFFFFFu - (unsigned)(w & 0xFFFFFFFFu);
        int n = (int)(flat >> 14);
        int t = (int)(flat & (T_LEN - 1));
        int L = min(t + ALEN, T_LEN - 1) - t;   // ref clips: position T-1 never written

        // ---- residual/recon update distributed across the group (16 elems/CTA) ----
        if (tid < 16) {
            int u = mem * 16 + tid;
            if (u < L) {
                float wv = v * g_dn[n * ALEN + u];
                out[(size_t)grp * T_LEN + t + u] -= wv;
                out[(size_t)(BATCH + grp) * T_LEN + t + u] += wv;
            }
        }
        if (it == N_ITER - 1) return;

        if (L > 0) {
            const int dlt = (t - (ALEN - 1)) & 1;     // window shift for even alignment
            const int toff2 = (t - (ALEN - 1)) - dlt; // even
            // tf32 splits of delta signal; support at u in [511+dlt, 511+dlt+L)
            for (int i = tid; i < SIGL; i += 256) {
                int j = i - (ALEN - 1) - dlt;
                float sv = (j >= 0 && j < L) ? v * g_dn[n * ALEN + j] : 0.f;
                uint32_t big = f2tf32(sv);
                sS[i] = big;
                sS[SSL + i] = f2tf32(sv - __uint_as_float(big));
            }
            __syncthreads();

            #pragma unroll
            for (int pass = 0; pass < 2; pass++) {
                int tw = pass * 512 + wid * 64;
                int klo = max(0, (ALEN - 1) + dlt - (tw + 63)) & ~7;
                int khi = min(ALEN, (ALEN - 1) + dlt + L - tw);
                khi = (khi + 7) & ~7;
                if (klo >= khi) continue;

                float acc[8][4];
                #pragma unroll
                for (int ni = 0; ni < 8; ni++)
                    #pragma unroll
                    for (int q = 0; q < 4; q++) acc[ni][q] = 0.f;

                for (int k0 = klo; k0 < khi; k0 += 8) {
                    int col = k0 + tig;
                    uint32_t Ab[4], As[4], Bb[8][2], Bs[8][2];
                    {
                        const uint32_t* p = &sA[g * KSTR + col];
                        Ab[0] = p[0];
                        Ab[1] = p[8 * KSTR];
                        Ab[2] = p[4];
                        Ab[3] = p[8 * KSTR + 4];
                        const uint32_t* q = p + 16 * KSTR;
                        As[0] = q[0];
                        As[1] = q[8 * KSTR];
                        As[2] = q[4];
                        As[3] = q[8 * KSTR + 4];
                    }
                    #pragma unroll
                    for (int ni = 0; ni < 8; ni++) {
                        int idx = tw + ni * 8 + g + col;
                        Bb[ni][0] = sS[idx];
                        Bb[ni][1] = sS[idx + 4];
                        Bs[ni][0] = sS[SSL + idx];
                        Bs[ni][1] = sS[SSL + idx + 4];
                    }
                    #pragma unroll
                    for (int ni = 0; ni < 8; ni++) {
                        mma8(acc[ni], As, Bb[ni]);
                        mma8(acc[ni], Ab, Bs[ni]);
                        mma8(acc[ni], Ab, Bb[ni]);
                    }
                }

                // float2 RMW epilogue (tt even; out-of-support acc are exact zeros)
                {
                    int n1 = n0 + g;
                    float* row1 = g_fm + ((size_t)(grp * NATOMS + n1)) * T_LEN;
                    float* row2 = row1 + 8 * (size_t)T_LEN;
                    #pragma unroll
                    for (int ni = 0; ni < 8; ni++) {
                        int tt = toff2 + tw + ni * 8 + tig * 2;
                        if (tt >= 0 && tt < T_LEN) {
                            float2 a = *(float2*)(row1 + tt);
                            a.x -= acc[ni][0];
                            a.y -= acc[ni][1];
                            *(float2*)(row1 + tt) = a;
                            float2 c = *(float2*)(row2 + tt);
                            c.x -= acc[ni][2];
                            c.y -= acc[ni][3];
                            *(float2*)(row2 + tt) = c;
                        }
                    }
                }
            }
            __syncthreads();   // delta stores visible CTA-wide before refresh reads

            // ---- refresh own rows' touched block maxima -> smem keys ----
            {
                int lo = max(0, t - (ALEN - 1));
                int hi = min(T_LEN - 1, t + (ALEN - 1));
                int bl0 = lo >> 10, bl1 = hi >> 10;
                for (int u = wid; u < 32; u += 8) {
                    int r = u >> 1;
                    int which = u & 1;
                    if (which && bl1 == bl0) continue;
                    int bl = which ? bl1 : bl0;
                    const float* row = &g_fm[((size_t)(grp * NATOMS + n0 + r)) * T_LEN + bl * BLKSZ];
                    float bv = -3.402823466e38f;
                    int bt = 0x7FFFFFFF;
                    #pragma unroll
                    for (int i = 0; i < 8; i++) {
                        int base = (i * 32 + lane) * 4;
                        float4 vv = *(const float4*)&row[base];
                        if (vv.x > bv) { bv = vv.x; bt = base; }
                        if (vv.y > bv) { bv = vv.y; bt = base + 1; }
                        if (vv.z > bv) { bv = vv.z; bt = base + 2; }
                        if (vv.w > bv) { bv = vv.w; bt = base + 3; }
                    }
                    #pragma unroll
                    for (int o = 16; o > 0; o >>= 1) {
                        float ov = __shfl_down_sync(0xFFFFFFFFu, bv, o);
                        int   ot = __shfl_down_sync(0xFFFFFFFFu, bt, o);
                        if (ov > bv || (ov == bv && ot < bt)) { bv = ov; bt = ot; }
                    }
                    if (lane == 0)
                        sBK[r * NBLK + bl] =
                            pack_key(bv, (unsigned)((n0 + r) * T_LEN + bl * BLKSZ + bt));
                }
            }
        }
        __syncthreads();   // sBK updates visible CTA-wide

        // ---- A-scan for it+1 from smem keys ----
        {
            unsigned long long best = sBK[tid];
            #pragma unroll
            for (int o = 16; o > 0; o >>= 1) {
                unsigned long long ok = __shfl_down_sync(0xFFFFFFFFu, best, o);
                if (ok > best) best = ok;
            }
            if (lane == 0) s_part[wid] = best;
            __syncthreads();
            if (wid == 0) {
                unsigned long long b2 = (lane < 8) ? s_part[lane] : 0ull;
                #pragma unroll
                for (int o = 4; o > 0; o >>= 1) {
                    unsigned long long ok = __shfl_down_sync(0xFFFFFFFFu, b2, o);
                    if (ok > b2) b2 = ok;
                }
                if (lane == 0) atomicMax(&g_best[(it + 1) * BATCH + grp], b2);
            }
        }
        gsync_grp(grp);
    }
}

// ---------------- launch ----------------
extern "C" void kernel_launch(void* const* d_in, const int* in_sizes, int n_in,
                              void* d_out, int out_size) {
    const float* x = (const float*)d_in[0];
    const float* d = (const float*)d_in[1];
    float* out = (float*)d_out;

    cudaFuncSetAttribute(k_conv_full, cudaFuncAttributeMaxDynamicSharedMemorySize, CONV_SMEM);
    cudaFuncSetAttribute(k_loop,      cudaFuncAttributeMaxDynamicSharedMemorySize, LOOP_SMEM);

    k_norm<<<NATOMS, 256>>>(d);
    {
        int n = BATCH * T_LEN;
        k_init_out<<<(n + 255) / 256, 256>>>(x, out);
    }
    k_conv_full<<<dim3(T_LEN / TNP, NATOMS / TM_C, BATCH), 256, CONV_SMEM>>>(x);
    k_bmax_init<<<BATCH * NATOMS * NBLK / 8, 256>>>();
    k_loop<<<PCTAS, 256, LOOP_SMEM>>>(out);
}